// round 7
// baseline (speedup 1.0000x reference)
#include <cuda_runtime.h>
#include <cstdint>

#define D_MODEL 768
#define D3      2304
#define DFF     3072
#define NHEAD   12
#define SEQ     4096
#define BATCH   2
#define MROWS   (BATCH*SEQ)   // 8192

// ------------------------- scratch (device globals; no runtime alloc) -----
__device__ float g_qkv[MROWS * D3];
__device__ float g_ctx[MROWS * D_MODEL];
__device__ float g_y  [MROWS * D_MODEL];
__device__ float g_x  [MROWS * D_MODEL];
__device__ float g_h  [MROWS * DFF];

// ------------------------- helpers ---------------------------------------
__device__ __forceinline__ uint32_t f2tf(float f) {
    uint32_t r;
    asm("cvt.rna.tf32.f32 %0, %1;" : "=r"(r) : "f"(f));
    return r;
}

__device__ __forceinline__ void mma_tf32(float* c, const uint32_t* a, const uint32_t* b) {
    asm volatile(
        "mma.sync.aligned.m16n8k8.row.col.f32.tf32.tf32.f32 "
        "{%0,%1,%2,%3},{%4,%5,%6,%7},{%8,%9},{%0,%1,%2,%3};"
        : "+f"(c[0]), "+f"(c[1]), "+f"(c[2]), "+f"(c[3])
        : "r"(a[0]), "r"(a[1]), "r"(a[2]), "r"(a[3]), "r"(b[0]), "r"(b[1]));
}

__device__ __forceinline__ uint32_t su32(const void* p) {
    return (uint32_t)__cvta_generic_to_shared(p);
}

// ldmatrix x4: lanes 0-7 address matrix0 rows, 8-15 m1, 16-23 m2, 24-31 m3.
__device__ __forceinline__ void ldsm4(uint32_t* r, uint32_t addr) {
    asm volatile(
        "ldmatrix.sync.aligned.m8n8.x4.shared.b16 {%0,%1,%2,%3}, [%4];"
        : "=r"(r[0]), "=r"(r[1]), "=r"(r[2]), "=r"(r[3]) : "r"(addr));
}

// ------------------------- TF32 tensor-core GEMM (ldmatrix) ---------------
// C(MxN) = A(MxK) * W(NxK)^T + bias [+res][relu]
// 128x128 tile, BK=16, 256 threads (8 warps, warp tile 64x32).
// smem [row][k], row stride 20 words -> LDSM chunks hit distinct bank groups.
#define GPAD 20

__global__ __launch_bounds__(256) void gemm_tc(
    const float* __restrict__ A, const float* __restrict__ W,
    const float* __restrict__ bias, const float* __restrict__ res,
    float* __restrict__ C, int M, int N, int K, int relu)
{
    __shared__ uint32_t As[2][128 * GPAD];
    __shared__ uint32_t Bs[2][128 * GPAD];

    const int tid  = threadIdx.x;
    const int warp = tid >> 5;
    const int lane = tid & 31;
    const int g = lane >> 2;
    const int t = lane & 3;
    const int wm = warp >> 2;        // m offset wm*64
    const int wn = warp & 3;         // n offset wn*32

    const int bm0 = blockIdx.y * 128;
    const int bn0 = blockIdx.x * 128;

    // LDSM lane-address components
    const int arow  = lane & 15;             // A: row within 16-row pair-group
    const int aword = (lane >> 4) << 2;      // A: word +0 / +4
    const int brow  = (lane & 7) + ((lane & 16) ? 8 : 0);  // B: row
    const int bword = (lane & 8) ? 4 : 0;                  // B: word +0 / +4

    const uint32_t sA = su32(As);
    const uint32_t sB = su32(Bs);
    const uint32_t aoff = ((wm * 64 + arow) * GPAD + aword) * 4;
    const uint32_t boff = ((wn * 32 + brow) * GPAD + bword) * 4;

    // global load mapping: thread covers rows lm, lm+64; k-quad lq
    const int lm = tid >> 2;
    const int lq = tid & 3;
    const float* Ap = A + (size_t)(bm0 + lm) * K + 4 * lq;
    const float* Wp = W + (size_t)(bn0 + lm) * K + 4 * lq;
    const size_t strA = (size_t)64 * K;

    float acc[4][4][4];
#pragma unroll
    for (int i = 0; i < 4; ++i)
#pragma unroll
        for (int j = 0; j < 4; ++j)
#pragma unroll
            for (int r = 0; r < 4; ++r) acc[i][j][r] = 0.f;

    const int NT = K / 16;

    // preload tile 0
    float4 a0 = *(const float4*)(Ap);
    float4 a1 = *(const float4*)(Ap + strA);
    float4 b0 = *(const float4*)(Wp);
    float4 b1 = *(const float4*)(Wp + strA);
    {
        uint32_t* as = As[0] + lm * GPAD + 4 * lq;
        as[0] = f2tf(a0.x); as[1] = f2tf(a0.y); as[2] = f2tf(a0.z); as[3] = f2tf(a0.w);
        uint32_t* as2 = As[0] + (lm + 64) * GPAD + 4 * lq;
        as2[0] = f2tf(a1.x); as2[1] = f2tf(a1.y); as2[2] = f2tf(a1.z); as2[3] = f2tf(a1.w);
        uint32_t* bs = Bs[0] + lm * GPAD + 4 * lq;
        bs[0] = f2tf(b0.x); bs[1] = f2tf(b0.y); bs[2] = f2tf(b0.z); bs[3] = f2tf(b0.w);
        uint32_t* bs2 = Bs[0] + (lm + 64) * GPAD + 4 * lq;
        bs2[0] = f2tf(b1.x); bs2[1] = f2tf(b1.y); bs2[2] = f2tf(b1.z); bs2[3] = f2tf(b1.w);
    }
    __syncthreads();

    for (int it = 0; it < NT; ++it) {
        float4 na0, na1, nb0, nb1;
        if (it + 1 < NT) {
            int k0 = (it + 1) * 16;
            na0 = *(const float4*)(Ap + k0);
            na1 = *(const float4*)(Ap + strA + k0);
            nb0 = *(const float4*)(Wp + k0);
            nb1 = *(const float4*)(Wp + strA + k0);
        }
        const uint32_t abase = sA + (uint32_t)((it & 1) * 128 * GPAD * 4) + aoff;
        const uint32_t bbase = sB + (uint32_t)((it & 1) * 128 * GPAD * 4) + boff;
#pragma unroll
        for (int ks = 0; ks < 2; ++ks) {
            const int kd = ks * 8;
            uint32_t af[4][4], bfr[2][4];
#pragma unroll
            for (int mt = 0; mt < 4; ++mt)
                ldsm4(af[mt], abase + (mt * 16 * GPAD + kd) * 4);
#pragma unroll
            for (int p = 0; p < 2; ++p)
                ldsm4(bfr[p], bbase + (p * 16 * GPAD + kd) * 4);
#pragma unroll
            for (int mt = 0; mt < 4; ++mt)
#pragma unroll
                for (int nt = 0; nt < 4; ++nt)
                    mma_tf32(acc[mt][nt], af[mt], &bfr[nt >> 1][(nt & 1) * 2]);
        }
        if (it + 1 < NT) {
            uint32_t* das = As[(it + 1) & 1] + lm * GPAD + 4 * lq;
            das[0] = f2tf(na0.x); das[1] = f2tf(na0.y); das[2] = f2tf(na0.z); das[3] = f2tf(na0.w);
            uint32_t* das2 = As[(it + 1) & 1] + (lm + 64) * GPAD + 4 * lq;
            das2[0] = f2tf(na1.x); das2[1] = f2tf(na1.y); das2[2] = f2tf(na1.z); das2[3] = f2tf(na1.w);
            uint32_t* dbs = Bs[(it + 1) & 1] + lm * GPAD + 4 * lq;
            dbs[0] = f2tf(nb0.x); dbs[1] = f2tf(nb0.y); dbs[2] = f2tf(nb0.z); dbs[3] = f2tf(nb0.w);
            uint32_t* dbs2 = Bs[(it + 1) & 1] + (lm + 64) * GPAD + 4 * lq;
            dbs2[0] = f2tf(nb1.x); dbs2[1] = f2tf(nb1.y); dbs2[2] = f2tf(nb1.z); dbs2[3] = f2tf(nb1.w);
        }
        __syncthreads();
    }

    // epilogue: bias + optional residual + relu
#pragma unroll
    for (int nt = 0; nt < 4; ++nt) {
        const int n = bn0 + wn * 32 + nt * 8 + 2 * t;
        const float2 bv = *(const float2*)(bias + n);
#pragma unroll
        for (int mt = 0; mt < 4; ++mt) {
            const int r0 = bm0 + wm * 64 + mt * 16 + g;
            const int r1 = r0 + 8;
            float2 v0 = make_float2(acc[mt][nt][0] + bv.x, acc[mt][nt][1] + bv.y);
            float2 v1 = make_float2(acc[mt][nt][2] + bv.x, acc[mt][nt][3] + bv.y);
            if (res) {
                float2 q0 = *(const float2*)(res + (size_t)r0 * N + n);
                float2 q1 = *(const float2*)(res + (size_t)r1 * N + n);
                v0.x += q0.x; v0.y += q0.y; v1.x += q1.x; v1.y += q1.y;
            }
            if (relu) {
                v0.x = fmaxf(v0.x, 0.f); v0.y = fmaxf(v0.y, 0.f);
                v1.x = fmaxf(v1.x, 0.f); v1.y = fmaxf(v1.y, 0.f);
            }
            *(float2*)(C + (size_t)r0 * N + n) = v0;
            *(float2*)(C + (size_t)r1 * N + n) = v1;
        }
    }
}

// ------------------------- TF32 flash attention (ldmatrix) ----------------
// Bq=Bk=64, dh=64. QK^T and PV via m16n8k8 mma, softmax fp32.
// Q/K/P: [row][k] pad 68.  V stored transposed [d][j] pad 68.
#define PQ 68
#define ATTN_SMEM ((4 * 64 * PQ + 3 * 64) * 4)

__global__ __launch_bounds__(256) void attn_tc(
    const float* __restrict__ qkv, float* __restrict__ ctx)
{
    extern __shared__ float sm[];
    float* Qs = sm;                 // [q][d] pad 68
    float* Ks = Qs + 64 * PQ;       // [j][d] pad 68
    float* Ps = Ks + 64 * PQ;       // [q][j] pad 68
    float* Vs = Ps + 64 * PQ;       // [d][j] pad 68 (transposed)
    float* ms = Vs + 64 * PQ;
    float* ls = ms + 64;
    float* rs = ls + 64;
    uint32_t* Qu = (uint32_t*)Qs;
    uint32_t* Ku = (uint32_t*)Ks;
    uint32_t* Pu = (uint32_t*)Ps;
    uint32_t* Vu = (uint32_t*)Vs;

    const int tid  = threadIdx.x;
    const int lane = tid & 31;
    const int warp = tid >> 5;
    const int g = lane >> 2;
    const int t = lane & 3;
    const int wq = warp >> 1;
    const int wj = warp & 1;
    const int q0w = wq * 16;

    // LDSM lane-address components
    const int arow  = lane & 15;
    const int aword = (lane >> 4) << 2;
    const int brow  = (lane & 7) + ((lane & 16) ? 8 : 0);
    const int bword = (lane & 8) ? 4 : 0;

    const uint32_t qaddr = su32(Qu) + ((q0w + arow) * PQ + aword) * 4;
    const uint32_t paddr = su32(Pu) + ((q0w + arow) * PQ + aword) * 4;
    uint32_t kaddr[2], vaddr[2];
#pragma unroll
    for (int p = 0; p < 2; ++p) {
        kaddr[p] = su32(Ku) + ((wj * 32 + p * 16 + brow) * PQ + bword) * 4;
        vaddr[p] = su32(Vu) + ((wj * 32 + p * 16 + brow) * PQ + bword) * 4;
    }

    const int bh = blockIdx.y;
    const int b = bh / NHEAD, h = bh % NHEAD;
    const int q0 = blockIdx.x * 64;
    const float* Qg = qkv + ((size_t)(b * SEQ + q0)) * D3 + h * 64;
    const float* Kg = qkv + ((size_t)(b * SEQ)) * D3 + D_MODEL + h * 64;
    const float* Vg = Kg + D_MODEL;

    if (tid < 64) { ms[tid] = -1e30f; ls[tid] = 0.f; }

    // load Q tile (tf32)
    {
        const int jr = tid >> 2;
        const int dc = (tid & 3) * 4;
#pragma unroll
        for (int p = 0; p < 4; ++p) {
            int d = dc + p * 16;
            float4 v = *(const float4*)(Qg + (size_t)jr * D3 + d);
            uint32_t* dst = Qu + jr * PQ + d;
            dst[0] = f2tf(v.x); dst[1] = f2tf(v.y);
            dst[2] = f2tf(v.z); dst[3] = f2tf(v.w);
        }
    }

    float accO[4][4];
#pragma unroll
    for (int i = 0; i < 4; ++i)
#pragma unroll
        for (int j = 0; j < 4; ++j) accO[i][j] = 0.f;

    for (int j0 = 0; j0 < SEQ; j0 += 64) {
        __syncthreads();
        {
            const int jr = tid >> 2;
            const int dc = (tid & 3) * 4;
#pragma unroll
            for (int p = 0; p < 4; ++p) {
                int d = dc + p * 16;
                size_t go = (size_t)(j0 + jr) * D3 + d;
                float4 kv = *(const float4*)(Kg + go);
                uint32_t* kd = Ku + jr * PQ + d;
                kd[0] = f2tf(kv.x); kd[1] = f2tf(kv.y);
                kd[2] = f2tf(kv.z); kd[3] = f2tf(kv.w);
                float4 vv = *(const float4*)(Vg + go);   // V transposed: [d][j]
                Vu[(d + 0) * PQ + jr] = f2tf(vv.x);
                Vu[(d + 1) * PQ + jr] = f2tf(vv.y);
                Vu[(d + 2) * PQ + jr] = f2tf(vv.z);
                Vu[(d + 3) * PQ + jr] = f2tf(vv.w);
            }
        }
        __syncthreads();

        // S = Q K^T (warp: 16q x 32j), 8 k8 steps
        float sacc[4][4];
#pragma unroll
        for (int i = 0; i < 4; ++i)
#pragma unroll
            for (int j = 0; j < 4; ++j) sacc[i][j] = 0.f;
#pragma unroll
        for (int ks = 0; ks < 8; ++ks) {
            const int kd = ks * 8;
            uint32_t af[4], bfr[2][4];
            ldsm4(af, qaddr + kd * 4);
#pragma unroll
            for (int p = 0; p < 2; ++p)
                ldsm4(bfr[p], kaddr[p] + kd * 4);
#pragma unroll
            for (int nt = 0; nt < 4; ++nt)
                mma_tf32(sacc[nt], af, &bfr[nt >> 1][(nt & 1) * 2]);
        }
        const float scale = 0.125f;
#pragma unroll
        for (int nt = 0; nt < 4; ++nt) {
            int j = wj * 32 + nt * 8 + 2 * t;
            *(float2*)(Ps + (q0w + g) * PQ + j) =
                make_float2(sacc[nt][0] * scale, sacc[nt][1] * scale);
            *(float2*)(Ps + (q0w + g + 8) * PQ + j) =
                make_float2(sacc[nt][2] * scale, sacc[nt][3] * scale);
        }
        __syncthreads();

        // online softmax: 4 threads/row, 16 cols each
        {
            const int q = tid >> 2;
            const int pt = tid & 3;
            float* Pq = Ps + q * PQ + pt * 16;
            float mo = ms[q];
            float mx = -1e30f;
#pragma unroll
            for (int i = 0; i < 16; ++i) mx = fmaxf(mx, Pq[i]);
            mx = fmaxf(mx, __shfl_xor_sync(0xffffffffu, mx, 1));
            mx = fmaxf(mx, __shfl_xor_sync(0xffffffffu, mx, 2));
            mx = fmaxf(mx, mo);
            float sum = 0.f;
            uint32_t* Pqi = (uint32_t*)Pq;
#pragma unroll
            for (int i = 0; i < 16; ++i) {
                float e = __expf(Pq[i] - mx);
                sum += e;
                Pqi[i] = f2tf(e);
            }
            sum += __shfl_xor_sync(0xffffffffu, sum, 1);
            sum += __shfl_xor_sync(0xffffffffu, sum, 2);
            if (pt == 0) {
                float r = __expf(mo - mx);
                ls[q] = ls[q] * r + sum;
                ms[q] = mx;
                rs[q] = r;
            }
        }
        __syncthreads();

        // rescale, then O += P V (warp: 16q x 32d), 8 k8 steps over j
        const float rlo = rs[q0w + g];
        const float rhi = rs[q0w + g + 8];
#pragma unroll
        for (int nt = 0; nt < 4; ++nt) {
            accO[nt][0] *= rlo; accO[nt][1] *= rlo;
            accO[nt][2] *= rhi; accO[nt][3] *= rhi;
        }
#pragma unroll
        for (int ks = 0; ks < 8; ++ks) {
            const int kj = ks * 8;
            uint32_t af[4], bfr[2][4];
            ldsm4(af, paddr + kj * 4);
#pragma unroll
            for (int p = 0; p < 2; ++p)
                ldsm4(bfr[p], vaddr[p] + kj * 4);
#pragma unroll
            for (int nt = 0; nt < 4; ++nt)
                mma_tf32(accO[nt], af, &bfr[nt >> 1][(nt & 1) * 2]);
        }
    }

    const float ilo = 1.0f / ls[q0w + g];
    const float ihi = 1.0f / ls[q0w + g + 8];
    float* Og = ctx + ((size_t)(b * SEQ + q0)) * D_MODEL + h * 64;
#pragma unroll
    for (int nt = 0; nt < 4; ++nt) {
        int d = wj * 32 + nt * 8 + 2 * t;
        *(float2*)(Og + (size_t)(q0w + g) * D_MODEL + d) =
            make_float2(accO[nt][0] * ilo, accO[nt][1] * ilo);
        *(float2*)(Og + (size_t)(q0w + g + 8) * D_MODEL + d) =
            make_float2(accO[nt][2] * ihi, accO[nt][3] * ihi);
    }
}

// ------------------------- row LayerNorm ---------------------------------
__global__ __launch_bounds__(256) void ln_kernel(
    const float* __restrict__ y, const float* __restrict__ g,
    const float* __restrict__ be, float* __restrict__ o)
{
    const int row = blockIdx.x;
    const float* x = y + (size_t)row * D_MODEL;
    const int t = threadIdx.x;
    float v0 = x[t], v1 = x[t + 256], v2 = x[t + 512];
    float s = v0 + v1 + v2;
    float q = v0 * v0 + v1 * v1 + v2 * v2;
#pragma unroll
    for (int off = 16; off; off >>= 1) {
        s += __shfl_xor_sync(0xffffffffu, s, off);
        q += __shfl_xor_sync(0xffffffffu, q, off);
    }
    __shared__ float ss[8], sq[8];
    __shared__ float s_mu, s_inv;
    int w = t >> 5, l = t & 31;
    if (l == 0) { ss[w] = s; sq[w] = q; }
    __syncthreads();
    if (t == 0) {
        float S = 0.f, Q = 0.f;
#pragma unroll
        for (int i = 0; i < 8; ++i) { S += ss[i]; Q += sq[i]; }
        float mu = S * (1.0f / D_MODEL);
        float var = Q * (1.0f / D_MODEL) - mu * mu;
        s_mu = mu;
        s_inv = rsqrtf(var + 1e-5f);
    }
    __syncthreads();
    float mu = s_mu, inv = s_inv;
    float* op = o + (size_t)row * D_MODEL;
    op[t]       = (v0 - mu) * inv * g[t]       + be[t];
    op[t + 256] = (v1 - mu) * inv * g[t + 256] + be[t + 256];
    op[t + 512] = (v2 - mu) * inv * g[t + 512] + be[t + 512];
}

// ------------------------- launch ----------------------------------------
extern "C" void kernel_launch(void* const* d_in, const int* in_sizes, int n_in,
                              void* d_out, int out_size)
{
    const float* src   = (const float*)d_in[0];
    const float* w_qkv = (const float*)d_in[1];
    const float* b_qkv = (const float*)d_in[2];
    const float* w_out = (const float*)d_in[3];
    const float* b_out = (const float*)d_in[4];
    const float* w1    = (const float*)d_in[5];
    const float* b1    = (const float*)d_in[6];
    const float* w2    = (const float*)d_in[7];
    const float* b2    = (const float*)d_in[8];
    const float* ln1w  = (const float*)d_in[9];
    const float* ln1b  = (const float*)d_in[10];
    const float* ln2w  = (const float*)d_in[11];
    const float* ln2b  = (const float*)d_in[12];
    float* out = (float*)d_out;

    float *qkv, *ctx, *y, *x, *hb;
    cudaGetSymbolAddress((void**)&qkv, g_qkv);
    cudaGetSymbolAddress((void**)&ctx, g_ctx);
    cudaGetSymbolAddress((void**)&y,   g_y);
    cudaGetSymbolAddress((void**)&x,   g_x);
    cudaGetSymbolAddress((void**)&hb,  g_h);

    cudaFuncSetAttribute(attn_tc,
                         cudaFuncAttributeMaxDynamicSharedMemorySize, ATTN_SMEM);

    dim3 thr(256);
    // 1) QKV projection
    gemm_tc<<<dim3(D3 / 128, MROWS / 128), thr>>>(
        src, w_qkv, b_qkv, nullptr, qkv, MROWS, D3, D_MODEL, 0);
    // 2) flash attention
    attn_tc<<<dim3(SEQ / 64, BATCH * NHEAD), thr, ATTN_SMEM>>>(qkv, ctx);
    // 3) out projection + residual(src)
    gemm_tc<<<dim3(D_MODEL / 128, MROWS / 128), thr>>>(
        ctx, w_out, b_out, src, y, MROWS, D_MODEL, D_MODEL, 0);
    // 4) LN1
    ln_kernel<<<MROWS, 256>>>(y, ln1w, ln1b, x);
    // 5) FFN1 + relu
    gemm_tc<<<dim3(DFF / 128, MROWS / 128), thr>>>(
        x, w1, b1, nullptr, hb, MROWS, DFF, D_MODEL, 1);
    // 6) FFN2 + residual(x)
    gemm_tc<<<dim3(D_MODEL / 128, MROWS / 128), thr>>>(
        hb, w2, b2, x, y, MROWS, D_MODEL, DFF, 0);
    // 7) LN2
    ln_kernel<<<MROWS, 256>>>(y, ln2w, ln2b, out);
}

// round 9
// speedup vs baseline: 1.0394x; 1.0394x over previous
#include <cuda_runtime.h>
#include <cstdint>

#define D_MODEL 768
#define D3      2304
#define DFF     3072
#define NHEAD   12
#define SEQ     4096
#define BATCH   2
#define MROWS   (BATCH*SEQ)   // 8192

// ------------------------- scratch (device globals; no runtime alloc) -----
__device__ float g_qkv[MROWS * D3];
__device__ float g_ctx[MROWS * D_MODEL];
__device__ float g_y  [MROWS * D_MODEL];
__device__ float g_x  [MROWS * D_MODEL];
__device__ float g_h  [MROWS * DFF];

// ------------------------- helpers ---------------------------------------
__device__ __forceinline__ void mma_tf32(float* c, const uint32_t* a, const uint32_t* b) {
    asm volatile(
        "mma.sync.aligned.m16n8k8.row.col.f32.tf32.tf32.f32 "
        "{%0,%1,%2,%3},{%4,%5,%6,%7},{%8,%9},{%0,%1,%2,%3};"
        : "+f"(c[0]), "+f"(c[1]), "+f"(c[2]), "+f"(c[3])
        : "r"(a[0]), "r"(a[1]), "r"(a[2]), "r"(a[3]), "r"(b[0]), "r"(b[1]));
}

__device__ __forceinline__ uint32_t su32(const void* p) {
    return (uint32_t)__cvta_generic_to_shared(p);
}

__device__ __forceinline__ void cpa16(uint32_t dst, const float* src) {
    asm volatile("cp.async.cg.shared.global [%0], [%1], 16;" :: "r"(dst), "l"(src));
}
#define CP_COMMIT() asm volatile("cp.async.commit_group;" ::: "memory")
#define CP_WAIT0()  asm volatile("cp.async.wait_group 0;" ::: "memory")

// ------------------------- TF32 GEMM, cp.async pipelined ------------------
// C(MxN) = A(MxK) * W(NxK)^T + bias [+res][relu]
// 128x128 tile, BK=32, 256 threads (8 warps, warp tile 64x32), 2-stage
// cp.async double buffer, raw fp32 bits into tf32 mma (HW truncates).
#define GPAD 36                    // words per row (32 data + 4 pad)
#define GSTG (128 * GPAD)          // words per matrix per stage
#define GEMM_SMEM (4 * GSTG * 4)   // A[2] + B[2], bytes = 73728

__global__ __launch_bounds__(256) void gemm_tc(
    const float* __restrict__ A, const float* __restrict__ W,
    const float* __restrict__ bias, const float* __restrict__ res,
    float* __restrict__ C, int M, int N, int K, int relu)
{
    extern __shared__ uint32_t gsm[];
    uint32_t* As = gsm;              // [2][GSTG]
    uint32_t* Bs = gsm + 2 * GSTG;   // [2][GSTG]

    const int tid  = threadIdx.x;
    const int warp = tid >> 5;
    const int lane = tid & 31;
    const int g = lane >> 2;
    const int t = lane & 3;
    const int wm = warp >> 2;        // m offset wm*64
    const int wn = warp & 3;         // n offset wn*32

    const int bm0 = blockIdx.y * 128;
    const int bn0 = blockIdx.x * 128;

    // cp.async mapping: thread covers row r, 4 consecutive 16B chunks
    const int r  = tid >> 1;
    const int q0 = (tid & 1) * 4;    // quad base (quads of 4 floats)
    const float* Ap = A + (size_t)(bm0 + r) * K + q0 * 4;
    const float* Wp = W + (size_t)(bn0 + r) * K + q0 * 4;
    const uint32_t dstA = su32(As) + (r * GPAD + q0 * 4) * 4;
    const uint32_t dstB = su32(Bs) + (r * GPAD + q0 * 4) * 4;

    float acc[4][4][4];
#pragma unroll
    for (int i = 0; i < 4; ++i)
#pragma unroll
        for (int j = 0; j < 4; ++j)
#pragma unroll
            for (int c = 0; c < 4; ++c) acc[i][j][c] = 0.f;

    const int NT = K / 32;

    // prologue: stage 0 in flight
    {
        const float* pa = Ap;
        const float* pb = Wp;
#pragma unroll
        for (int c = 0; c < 4; ++c) {
            cpa16(dstA + c * 16, pa + c * 4);
            cpa16(dstB + c * 16, pb + c * 4);
        }
        CP_COMMIT();
    }

    for (int it = 0; it < NT; ++it) {
        CP_WAIT0();
        __syncthreads();
        if (it + 1 < NT) {
            const int kc = (it + 1) * 32;
            const uint32_t so = (uint32_t)(((it + 1) & 1) * GSTG * 4);
            const float* pa = Ap + kc;
            const float* pb = Wp + kc;
#pragma unroll
            for (int c = 0; c < 4; ++c) {
                cpa16(dstA + so + c * 16, pa + c * 4);
                cpa16(dstB + so + c * 16, pb + c * 4);
            }
            CP_COMMIT();
        }
        const uint32_t* as = As + (it & 1) * GSTG;
        const uint32_t* bs = Bs + (it & 1) * GSTG;
#pragma unroll
        for (int ks = 0; ks < 4; ++ks) {
            const int kd = ks * 8;
            uint32_t af[4][4], bf[4][2];
#pragma unroll
            for (int mt = 0; mt < 4; ++mt) {
                const int m = wm * 64 + mt * 16;
                af[mt][0] = as[(m + g) * GPAD + kd + t];
                af[mt][1] = as[(m + g + 8) * GPAD + kd + t];
                af[mt][2] = as[(m + g) * GPAD + kd + t + 4];
                af[mt][3] = as[(m + g + 8) * GPAD + kd + t + 4];
            }
#pragma unroll
            for (int nt = 0; nt < 4; ++nt) {
                const int n = wn * 32 + nt * 8;
                bf[nt][0] = bs[(n + g) * GPAD + kd + t];
                bf[nt][1] = bs[(n + g) * GPAD + kd + t + 4];
            }
#pragma unroll
            for (int mt = 0; mt < 4; ++mt)
#pragma unroll
                for (int nt = 0; nt < 4; ++nt)
                    mma_tf32(acc[mt][nt], af[mt], bf[nt]);
        }
    }

    // epilogue: bias + optional residual + relu
#pragma unroll
    for (int nt = 0; nt < 4; ++nt) {
        const int n = bn0 + wn * 32 + nt * 8 + 2 * t;
        const float2 bv = *(const float2*)(bias + n);
#pragma unroll
        for (int mt = 0; mt < 4; ++mt) {
            const int r0 = bm0 + wm * 64 + mt * 16 + g;
            const int r1 = r0 + 8;
            float2 v0 = make_float2(acc[mt][nt][0] + bv.x, acc[mt][nt][1] + bv.y);
            float2 v1 = make_float2(acc[mt][nt][2] + bv.x, acc[mt][nt][3] + bv.y);
            if (res) {
                float2 p0 = *(const float2*)(res + (size_t)r0 * N + n);
                float2 p1 = *(const float2*)(res + (size_t)r1 * N + n);
                v0.x += p0.x; v0.y += p0.y; v1.x += p1.x; v1.y += p1.y;
            }
            if (relu) {
                v0.x = fmaxf(v0.x, 0.f); v0.y = fmaxf(v0.y, 0.f);
                v1.x = fmaxf(v1.x, 0.f); v1.y = fmaxf(v1.y, 0.f);
            }
            *(float2*)(C + (size_t)r0 * N + n) = v0;
            *(float2*)(C + (size_t)r1 * N + n) = v1;
        }
    }
}

// ------------------------- TF32 flash attention ---------------------------
// Bq=128, Bk=64, dh=64. 256 threads = 8 warps, warp tile 16q x 64(j/d).
// K/V double-buffered via cp.async; Q fragments hoisted to registers.
// Raw fp32 bits into tf32 mma. Softmax fp32.
#define PK  68
#define PVV 72
#define QROWS 128
#define OFF_Q  0
#define OFF_K  (QROWS * PK)
#define OFF_V  (OFF_K + 2 * 64 * PK)
#define OFF_P  (OFF_V + 2 * 64 * PVV)
#define OFF_ST (OFF_P + QROWS * PK)
#define ATTN_SMEM ((OFF_ST + 3 * QROWS) * 4)   // 142848 bytes

__global__ __launch_bounds__(256) void attn_tc(
    const float* __restrict__ qkv, float* __restrict__ ctx)
{
    extern __shared__ uint32_t smu[];
    uint32_t* Qu = smu + OFF_Q;           // [128][PK]
    uint32_t* Ku = smu + OFF_K;           // [2][64][PK]
    uint32_t* Vu = smu + OFF_V;           // [2][64][PVV]
    uint32_t* Pu = smu + OFF_P;           // [128][PK] (S then P)
    float*    Ps = (float*)Pu;
    float*    ms = (float*)(smu + OFF_ST);
    float*    ls = ms + QROWS;
    float*    rs = ls + QROWS;

    const int tid  = threadIdx.x;
    const int lane = tid & 31;
    const int warp = tid >> 5;            // 0..7
    const int g = lane >> 2;
    const int t = lane & 3;
    const int q0w = warp * 16;

    const int bh = blockIdx.y;
    const int b = bh / NHEAD, h = bh % NHEAD;
    const int q0 = blockIdx.x * QROWS;
    const float* Qg = qkv + ((size_t)(b * SEQ + q0)) * D3 + h * 64;
    const float* Kg = qkv + ((size_t)(b * SEQ)) * D3 + D_MODEL + h * 64;
    const float* Vg = Kg + D_MODEL;

    if (tid < QROWS) { ms[tid] = -1e30f; ls[tid] = 0.f; }

    // Q tile via cp.async: row = tid>>1, 8 chunks from float (tid&1)*32
    {
        const int qr = tid >> 1;
        const int qq = (tid & 1) * 8;
        const float* src = Qg + (size_t)qr * D3 + qq * 4;
        const uint32_t dst = su32(Qu) + (qr * PK + qq * 4) * 4;
#pragma unroll
        for (int c = 0; c < 8; ++c) cpa16(dst + c * 16, src + c * 4);
    }

    // K/V cp.async mapping: row = tid>>2, 4 chunks from float (tid&3)*16
    const int kr = tid >> 2;
    const int kq = (tid & 3) * 4;
    const float* Ksrc = Kg + (size_t)kr * D3 + kq * 4;
    const float* Vsrc = Vg + (size_t)kr * D3 + kq * 4;
    const uint32_t kdst = su32(Ku) + (kr * PK + kq * 4) * 4;
    const uint32_t vdst = su32(Vu) + (kr * PVV + kq * 4) * 4;

    // stage 0
    {
#pragma unroll
        for (int c = 0; c < 4; ++c) {
            cpa16(kdst + c * 16, Ksrc + c * 4);
            cpa16(vdst + c * 16, Vsrc + c * 4);
        }
        CP_COMMIT();
    }
    CP_WAIT0();
    __syncthreads();

    // hoist Q fragments (loop-invariant)
    uint32_t qf[8][4];
#pragma unroll
    for (int ks = 0; ks < 8; ++ks) {
        const int kd = ks * 8;
        qf[ks][0] = Qu[(q0w + g) * PK + kd + t];
        qf[ks][1] = Qu[(q0w + g + 8) * PK + kd + t];
        qf[ks][2] = Qu[(q0w + g) * PK + kd + t + 4];
        qf[ks][3] = Qu[(q0w + g + 8) * PK + kd + t + 4];
    }

    float accO[8][4];
#pragma unroll
    for (int i = 0; i < 8; ++i)
#pragma unroll
        for (int j = 0; j < 4; ++j) accO[i][j] = 0.f;

    const int NJT = SEQ / 64;
    for (int jt = 0; jt < NJT; ++jt) {
        if (jt) { CP_WAIT0(); __syncthreads(); }
        if (jt + 1 < NJT) {
            const size_t jo = (size_t)(jt + 1) * 64 * D3;
            const uint32_t sk = (uint32_t)(((jt + 1) & 1) * 64 * PK * 4);
            const uint32_t sv = (uint32_t)(((jt + 1) & 1) * 64 * PVV * 4);
#pragma unroll
            for (int c = 0; c < 4; ++c) {
                cpa16(kdst + sk + c * 16, Ksrc + jo + c * 4);
                cpa16(vdst + sv + c * 16, Vsrc + jo + c * 4);
            }
            CP_COMMIT();
        }
        const uint32_t* Kb = Ku + (jt & 1) * 64 * PK;
        const uint32_t* Vb = Vu + (jt & 1) * 64 * PVV;

        // S = Q K^T  (warp: 16q x 64j)
        float sacc[8][4];
#pragma unroll
        for (int i = 0; i < 8; ++i)
#pragma unroll
            for (int j = 0; j < 4; ++j) sacc[i][j] = 0.f;
#pragma unroll
        for (int ks = 0; ks < 8; ++ks) {
            const int kd = ks * 8;
#pragma unroll
            for (int nt = 0; nt < 8; ++nt) {
                const int jn = nt * 8;
                uint32_t bf[2];
                bf[0] = Kb[(jn + g) * PK + kd + t];
                bf[1] = Kb[(jn + g) * PK + kd + t + 4];
                mma_tf32(sacc[nt], qf[ks], bf);
            }
        }
        const float scale = 0.125f;
#pragma unroll
        for (int nt = 0; nt < 8; ++nt) {
            const int j = nt * 8 + 2 * t;
            *(float2*)(Ps + (q0w + g) * PK + j) =
                make_float2(sacc[nt][0] * scale, sacc[nt][1] * scale);
            *(float2*)(Ps + (q0w + g + 8) * PK + j) =
                make_float2(sacc[nt][2] * scale, sacc[nt][3] * scale);
        }
        __syncthreads();

        // online softmax: 2 threads per row, 32 cols each
        {
            const int qrow = tid >> 1;
            const int ph = tid & 1;
            float* Pq = Ps + qrow * PK + ph * 32;
            const float mo = ms[qrow];
            float mx = -1e30f;
#pragma unroll
            for (int i = 0; i < 32; ++i) mx = fmaxf(mx, Pq[i]);
            mx = fmaxf(mx, __shfl_xor_sync(0xffffffffu, mx, 1));
            mx = fmaxf(mx, mo);
            float sum = 0.f;
#pragma unroll
            for (int i = 0; i < 32; ++i) {
                const float e = __expf(Pq[i] - mx);
                sum += e;
                Pq[i] = e;                      // raw fp32; mma truncates
            }
            sum += __shfl_xor_sync(0xffffffffu, sum, 1);
            if (ph == 0) {
                const float rr = __expf(mo - mx);
                ls[qrow] = ls[qrow] * rr + sum;
                ms[qrow] = mx;
                rs[qrow] = rr;
            }
        }
        __syncthreads();

        // rescale + O += P V  (warp: 16q x 64d)
        const float rlo = rs[q0w + g];
        const float rhi = rs[q0w + g + 8];
#pragma unroll
        for (int nt = 0; nt < 8; ++nt) {
            accO[nt][0] *= rlo; accO[nt][1] *= rlo;
            accO[nt][2] *= rhi; accO[nt][3] *= rhi;
        }
#pragma unroll
        for (int ks = 0; ks < 8; ++ks) {
            const int kj = ks * 8;
            uint32_t af[4];
            af[0] = Pu[(q0w + g) * PK + kj + t];
            af[1] = Pu[(q0w + g + 8) * PK + kj + t];
            af[2] = Pu[(q0w + g) * PK + kj + t + 4];
            af[3] = Pu[(q0w + g + 8) * PK + kj + t + 4];
#pragma unroll
            for (int nt = 0; nt < 8; ++nt) {
                const int dn = nt * 8;
                uint32_t bf[2];
                bf[0] = Vb[(kj + t) * PVV + dn + g];
                bf[1] = Vb[(kj + t + 4) * PVV + dn + g];
                mma_tf32(accO[nt], af, bf);
            }
        }
    }

    // write output
    const float ilo = 1.0f / ls[q0w + g];
    const float ihi = 1.0f / ls[q0w + g + 8];
    float* Og = ctx + ((size_t)(b * SEQ + q0)) * D_MODEL + h * 64;
#pragma unroll
    for (int nt = 0; nt < 8; ++nt) {
        const int d = nt * 8 + 2 * t;
        *(float2*)(Og + (size_t)(q0w + g) * D_MODEL + d) =
            make_float2(accO[nt][0] * ilo, accO[nt][1] * ilo);
        *(float2*)(Og + (size_t)(q0w + g + 8) * D_MODEL + d) =
            make_float2(accO[nt][2] * ihi, accO[nt][3] * ihi);
    }
}

// ------------------------- row LayerNorm ---------------------------------
__global__ __launch_bounds__(256) void ln_kernel(
    const float* __restrict__ y, const float* __restrict__ g,
    const float* __restrict__ be, float* __restrict__ o)
{
    const int row = blockIdx.x;
    const float* x = y + (size_t)row * D_MODEL;
    const int t = threadIdx.x;
    float v0 = x[t], v1 = x[t + 256], v2 = x[t + 512];
    float s = v0 + v1 + v2;
    float q = v0 * v0 + v1 * v1 + v2 * v2;
#pragma unroll
    for (int off = 16; off; off >>= 1) {
        s += __shfl_xor_sync(0xffffffffu, s, off);
        q += __shfl_xor_sync(0xffffffffu, q, off);
    }
    __shared__ float ss[8], sq[8];
    __shared__ float s_mu, s_inv;
    int w = t >> 5, l = t & 31;
    if (l == 0) { ss[w] = s; sq[w] = q; }
    __syncthreads();
    if (t == 0) {
        float S = 0.f, Q = 0.f;
#pragma unroll
        for (int i = 0; i < 8; ++i) { S += ss[i]; Q += sq[i]; }
        float mu = S * (1.0f / D_MODEL);
        float var = Q * (1.0f / D_MODEL) - mu * mu;
        s_mu = mu;
        s_inv = rsqrtf(var + 1e-5f);
    }
    __syncthreads();
    float mu = s_mu, inv = s_inv;
    float* op = o + (size_t)row * D_MODEL;
    op[t]       = (v0 - mu) * inv * g[t]       + be[t];
    op[t + 256] = (v1 - mu) * inv * g[t + 256] + be[t + 256];
    op[t + 512] = (v2 - mu) * inv * g[t + 512] + be[t + 512];
}

// ------------------------- launch ----------------------------------------
extern "C" void kernel_launch(void* const* d_in, const int* in_sizes, int n_in,
                              void* d_out, int out_size)
{
    const float* src   = (const float*)d_in[0];
    const float* w_qkv = (const float*)d_in[1];
    const float* b_qkv = (const float*)d_in[2];
    const float* w_out = (const float*)d_in[3];
    const float* b_out = (const float*)d_in[4];
    const float* w1    = (const float*)d_in[5];
    const float* b1    = (const float*)d_in[6];
    const float* w2    = (const float*)d_in[7];
    const float* b2    = (const float*)d_in[8];
    const float* ln1w  = (const float*)d_in[9];
    const float* ln1b  = (const float*)d_in[10];
    const float* ln2w  = (const float*)d_in[11];
    const float* ln2b  = (const float*)d_in[12];
    float* out = (float*)d_out;

    float *qkv, *ctx, *y, *x, *hb;
    cudaGetSymbolAddress((void**)&qkv, g_qkv);
    cudaGetSymbolAddress((void**)&ctx, g_ctx);
    cudaGetSymbolAddress((void**)&y,   g_y);
    cudaGetSymbolAddress((void**)&x,   g_x);
    cudaGetSymbolAddress((void**)&hb,  g_h);

    cudaFuncSetAttribute(gemm_tc,
                         cudaFuncAttributeMaxDynamicSharedMemorySize, GEMM_SMEM);
    cudaFuncSetAttribute(attn_tc,
                         cudaFuncAttributeMaxDynamicSharedMemorySize, ATTN_SMEM);

    dim3 thr(256);
    // 1) QKV projection
    gemm_tc<<<dim3(D3 / 128, MROWS / 128), thr, GEMM_SMEM>>>(
        src, w_qkv, b_qkv, nullptr, qkv, MROWS, D3, D_MODEL, 0);
    // 2) flash attention (Bq=128)
    attn_tc<<<dim3(SEQ / 128, BATCH * NHEAD), thr, ATTN_SMEM>>>(qkv, ctx);
    // 3) out projection + residual(src)
    gemm_tc<<<dim3(D_MODEL / 128, MROWS / 128), thr, GEMM_SMEM>>>(
        ctx, w_out, b_out, src, y, MROWS, D_MODEL, D_MODEL, 0);
    // 4) LN1
    ln_kernel<<<MROWS, 256>>>(y, ln1w, ln1b, x);
    // 5) FFN1 + relu
    gemm_tc<<<dim3(DFF / 128, MROWS / 128), thr, GEMM_SMEM>>>(
        x, w1, b1, nullptr, hb, MROWS, DFF, D_MODEL, 1);
    // 6) FFN2 + residual(x)
    gemm_tc<<<dim3(D_MODEL / 128, MROWS / 128), thr, GEMM_SMEM>>>(
        hb, w2, b2, x, y, MROWS, D_MODEL, DFF, 0);
    // 7) LN2
    ln_kernel<<<MROWS, 256>>>(y, ln2w, ln2b, out);
}

// round 11
// speedup vs baseline: 1.6976x; 1.6333x over previous
#include <cuda_runtime.h>
#include <cuda_bf16.h>
#include <cstdint>

#define D_MODEL 768
#define D3      2304
#define DFF     3072
#define NHEAD   12
#define SEQ     4096
#define BATCH   2
#define MROWS   (BATCH*SEQ)   // 8192

// ------------------------- scratch (device globals; no runtime alloc) -----
__device__ float          g_y [MROWS * D_MODEL];
__device__ float          g_x [MROWS * D_MODEL];
__device__ __nv_bfloat16  g_srcb[MROWS * D_MODEL];
__device__ __nv_bfloat16  g_qkvb[MROWS * D3];
__device__ __nv_bfloat16  g_ctxb[MROWS * D_MODEL];
__device__ __nv_bfloat16  g_xb  [MROWS * D_MODEL];
__device__ __nv_bfloat16  g_hb  [MROWS * DFF];
__device__ __nv_bfloat16  g_wqkvb[D3 * D_MODEL];
__device__ __nv_bfloat16  g_woutb[D_MODEL * D_MODEL];
__device__ __nv_bfloat16  g_w1b  [DFF * D_MODEL];
__device__ __nv_bfloat16  g_w2b  [D_MODEL * DFF];

// ------------------------- helpers ---------------------------------------
__device__ __forceinline__ uint32_t pack2(float lo, float hi) {
    uint32_t r;
    asm("cvt.rn.bf16x2.f32 %0, %2, %1;" : "=r"(r) : "f"(lo), "f"(hi));
    return r;
}

__device__ __forceinline__ void mma_bf16(float* c, const uint32_t* a, const uint32_t* b) {
    asm volatile(
        "mma.sync.aligned.m16n8k16.row.col.f32.bf16.bf16.f32 "
        "{%0,%1,%2,%3},{%4,%5,%6,%7},{%8,%9},{%0,%1,%2,%3};"
        : "+f"(c[0]), "+f"(c[1]), "+f"(c[2]), "+f"(c[3])
        : "r"(a[0]), "r"(a[1]), "r"(a[2]), "r"(a[3]), "r"(b[0]), "r"(b[1]));
}

__device__ __forceinline__ uint32_t su32(const void* p) {
    return (uint32_t)__cvta_generic_to_shared(p);
}

__device__ __forceinline__ void cpa16(uint32_t dst, const void* src) {
    asm volatile("cp.async.cg.shared.global [%0], [%1], 16;" :: "r"(dst), "l"(src));
}
#define CP_COMMIT() asm volatile("cp.async.commit_group;" ::: "memory")
#define CP_WAIT0()  asm volatile("cp.async.wait_group 0;" ::: "memory")

// ldmatrix x4 transpose (b16): B-fragments for PV from natural [j][d] V.
__device__ __forceinline__ void ldsm4t(uint32_t* r, uint32_t addr) {
    asm volatile(
        "ldmatrix.sync.aligned.m8n8.x4.trans.shared.b16 {%0,%1,%2,%3}, [%4];"
        : "=r"(r[0]), "=r"(r[1]), "=r"(r[2]), "=r"(r[3]) : "r"(addr));
}

// ------------------------- fp32 -> bf16 bulk convert ----------------------
__global__ __launch_bounds__(256) void f2b_kernel(
    const float* __restrict__ s, uint32_t* __restrict__ d, int n4)
{
    int i = blockIdx.x * blockDim.x + threadIdx.x;
    if (i < n4) {
        float4 v = ((const float4*)s)[i];
        d[2 * i]     = pack2(v.x, v.y);
        d[2 * i + 1] = pack2(v.z, v.w);
    }
}

// ------------------------- BF16 GEMM, cp.async pipelined ------------------
// C(MxN) = A(MxK) * W(NxK)^T + bias [+res f32][relu]; outputs fp32 and/or bf16.
// 128x128 tile, BK=32 elems (16 words/row, pad to 20), 256 threads, 2-stage.
#define GPW 20
#define GSTG (128 * GPW)

__global__ __launch_bounds__(256) void gemm_tc(
    const __nv_bfloat16* __restrict__ A, const __nv_bfloat16* __restrict__ W,
    const float* __restrict__ bias, const float* __restrict__ res,
    float* __restrict__ Cf, __nv_bfloat16* __restrict__ Cb,
    int M, int N, int K, int relu)
{
    __shared__ uint32_t As[2][GSTG];
    __shared__ uint32_t Bs[2][GSTG];

    const int tid  = threadIdx.x;
    const int warp = tid >> 5;
    const int lane = tid & 31;
    const int g = lane >> 2;
    const int t = lane & 3;
    const int wm = warp >> 2;
    const int wn = warp & 3;

    const int bm0 = blockIdx.y * 128;
    const int bn0 = blockIdx.x * 128;

    // cp.async: row r, two 16B chunks at chunk base c2
    const int r  = tid >> 1;
    const int c2 = (tid & 1) * 2;
    const __nv_bfloat16* Ap = A + (size_t)(bm0 + r) * K + c2 * 8;
    const __nv_bfloat16* Wp = W + (size_t)(bn0 + r) * K + c2 * 8;
    const uint32_t dA = su32(As) + (r * GPW + c2 * 4) * 4;
    const uint32_t dB = su32(Bs) + (r * GPW + c2 * 4) * 4;

    float acc[4][4][4];
#pragma unroll
    for (int i = 0; i < 4; ++i)
#pragma unroll
        for (int j = 0; j < 4; ++j)
#pragma unroll
            for (int c = 0; c < 4; ++c) acc[i][j][c] = 0.f;

    const int NT = K / 32;

    cpa16(dA, Ap);      cpa16(dA + 16, Ap + 8);
    cpa16(dB, Wp);      cpa16(dB + 16, Wp + 8);
    CP_COMMIT();

    for (int it = 0; it < NT; ++it) {
        CP_WAIT0();
        __syncthreads();
        if (it + 1 < NT) {
            const int kc = (it + 1) * 32;
            const uint32_t so = (uint32_t)(((it + 1) & 1) * GSTG * 4);
            cpa16(dA + so, Ap + kc);      cpa16(dA + so + 16, Ap + kc + 8);
            cpa16(dB + so, Wp + kc);      cpa16(dB + so + 16, Wp + kc + 8);
            CP_COMMIT();
        }
        const uint32_t* as = As[it & 1];
        const uint32_t* bs = Bs[it & 1];
#pragma unroll
        for (int ks = 0; ks < 2; ++ks) {
            const int kd = ks * 8;
            uint32_t af[4][4], bf[4][2];
#pragma unroll
            for (int mt = 0; mt < 4; ++mt) {
                const int m = wm * 64 + mt * 16;
                af[mt][0] = as[(m + g) * GPW + kd + t];
                af[mt][1] = as[(m + g + 8) * GPW + kd + t];
                af[mt][2] = as[(m + g) * GPW + kd + t + 4];
                af[mt][3] = as[(m + g + 8) * GPW + kd + t + 4];
            }
#pragma unroll
            for (int nt = 0; nt < 4; ++nt) {
                const int n = wn * 32 + nt * 8;
                bf[nt][0] = bs[(n + g) * GPW + kd + t];
                bf[nt][1] = bs[(n + g) * GPW + kd + t + 4];
            }
#pragma unroll
            for (int mt = 0; mt < 4; ++mt)
#pragma unroll
                for (int nt = 0; nt < 4; ++nt)
                    mma_bf16(acc[mt][nt], af[mt], bf[nt]);
        }
    }

    // epilogue: bias + optional residual + relu; fp32 and/or bf16 stores
#pragma unroll
    for (int nt = 0; nt < 4; ++nt) {
        const int n = bn0 + wn * 32 + nt * 8 + 2 * t;
        const float2 bv = *(const float2*)(bias + n);
#pragma unroll
        for (int mt = 0; mt < 4; ++mt) {
            const int r0 = bm0 + wm * 64 + mt * 16 + g;
            const int r1 = r0 + 8;
            float2 v0 = make_float2(acc[mt][nt][0] + bv.x, acc[mt][nt][1] + bv.y);
            float2 v1 = make_float2(acc[mt][nt][2] + bv.x, acc[mt][nt][3] + bv.y);
            if (res) {
                float2 p0 = *(const float2*)(res + (size_t)r0 * N + n);
                float2 p1 = *(const float2*)(res + (size_t)r1 * N + n);
                v0.x += p0.x; v0.y += p0.y; v1.x += p1.x; v1.y += p1.y;
            }
            if (relu) {
                v0.x = fmaxf(v0.x, 0.f); v0.y = fmaxf(v0.y, 0.f);
                v1.x = fmaxf(v1.x, 0.f); v1.y = fmaxf(v1.y, 0.f);
            }
            if (Cf) {
                *(float2*)(Cf + (size_t)r0 * N + n) = v0;
                *(float2*)(Cf + (size_t)r1 * N + n) = v1;
            }
            if (Cb) {
                *(uint32_t*)(Cb + (size_t)r0 * N + n) = pack2(v0.x, v0.y);
                *(uint32_t*)(Cb + (size_t)r1 * N + n) = pack2(v1.x, v1.y);
            }
        }
    }
}

// ------------------------- BF16 flash attention ---------------------------
// Bq=Bk=64, dh=64. 256 thr, warps (4q x 2j/d). bf16 qkv in, bf16 ctx out.
// K/V double-buffered cp.async; V natural [j][d], PV B-frags via ldsm.trans.
#define AW   36                 // words per 64-elem bf16 row (32 data + 4 pad)
#define SSP  68                 // fp32 score row pad
#define KSTG (64 * AW)          // words per K/V stage
#define OFF_Q  0
#define OFF_K  KSTG
#define OFF_V  (OFF_K + 2 * KSTG)
#define OFF_SS (OFF_V + 2 * KSTG)
#define OFF_P  (OFF_SS + 64 * SSP)
#define OFF_ST (OFF_P + 64 * AW)
#define ATTN_SMEM ((OFF_ST + 3 * 64) * 4)

__global__ __launch_bounds__(256) void attn_tc(
    const __nv_bfloat16* __restrict__ qkv, __nv_bfloat16* __restrict__ ctx)
{
    extern __shared__ uint32_t smu[];
    uint32_t* Qu = smu + OFF_Q;
    uint32_t* Ku = smu + OFF_K;
    uint32_t* Pu = smu + OFF_P;
    float*    Ss = (float*)(smu + OFF_SS);
    float*    ms = (float*)(smu + OFF_ST);
    float*    ls = ms + 64;
    float*    rs = ls + 64;

    const int tid  = threadIdx.x;
    const int lane = tid & 31;
    const int warp = tid >> 5;
    const int g = lane >> 2;
    const int t = lane & 3;
    const int wq = warp >> 1;
    const int wj = warp & 1;
    const int q0w = wq * 16;

    const int bh = blockIdx.y;
    const int b = bh / NHEAD, h = bh % NHEAD;
    const int q0 = blockIdx.x * 64;
    const __nv_bfloat16* Qg = qkv + ((size_t)(b * SEQ + q0)) * D3 + h * 64;
    const __nv_bfloat16* Kg = qkv + ((size_t)(b * SEQ)) * D3 + D_MODEL + h * 64;
    const __nv_bfloat16* Vg = Kg + D_MODEL;

    if (tid < 64) { ms[tid] = -1e30f; ls[tid] = 0.f; }

    // cp.async mapping: 64 rows x 8 chunks(16B), 4 thr/row, 2 chunks each
    const int ar = tid >> 2;
    const int ac = (tid & 3) * 2;
    const uint32_t qdst = su32(smu) + (OFF_Q + ar * AW + ac * 4) * 4;
    const uint32_t kdst = su32(smu) + (OFF_K + ar * AW + ac * 4) * 4;
    const uint32_t vdst = su32(smu) + (OFF_V + ar * AW + ac * 4) * 4;
    const __nv_bfloat16* Qsrc = Qg + (size_t)ar * D3 + ac * 8;
    const __nv_bfloat16* Ksrc = Kg + (size_t)ar * D3 + ac * 8;
    const __nv_bfloat16* Vsrc = Vg + (size_t)ar * D3 + ac * 8;

    cpa16(qdst, Qsrc);          cpa16(qdst + 16, Qsrc + 8);
    cpa16(kdst, Ksrc);          cpa16(kdst + 16, Ksrc + 8);
    cpa16(vdst, Vsrc);          cpa16(vdst + 16, Vsrc + 8);
    CP_COMMIT();
    CP_WAIT0();
    __syncthreads();

    // hoist Q fragments (loop-invariant)
    uint32_t qf[4][4];
#pragma unroll
    for (int ks = 0; ks < 4; ++ks) {
        const int kd = ks * 8;
        qf[ks][0] = Qu[(q0w + g) * AW + kd + t];
        qf[ks][1] = Qu[(q0w + g + 8) * AW + kd + t];
        qf[ks][2] = Qu[(q0w + g) * AW + kd + t + 4];
        qf[ks][3] = Qu[(q0w + g + 8) * AW + kd + t + 4];
    }

    // V ldsm.trans lane-address components
    const int vrow = (lane & 7) + ((lane & 8) ? 8 : 0);
    const int vcol = (lane & 16) ? 8 : 0;

    float accO[4][4];
#pragma unroll
    for (int i = 0; i < 4; ++i)
#pragma unroll
        for (int j = 0; j < 4; ++j) accO[i][j] = 0.f;

    const int NJT = SEQ / 64;
    for (int jt = 0; jt < NJT; ++jt) {
        if (jt) { CP_WAIT0(); __syncthreads(); }
        if (jt + 1 < NJT) {
            const size_t jo = (size_t)(jt + 1) * 64 * D3;
            const uint32_t so = (uint32_t)(((jt + 1) & 1) * KSTG * 4);
            cpa16(kdst + so, Ksrc + jo);      cpa16(kdst + so + 16, Ksrc + jo + 8);
            cpa16(vdst + so, Vsrc + jo);      cpa16(vdst + so + 16, Vsrc + jo + 8);
            CP_COMMIT();
        }
        const uint32_t* Kb = Ku + (jt & 1) * KSTG;
        const uint32_t vbase = su32(smu) + (OFF_V + (jt & 1) * KSTG) * 4;

        // S = Q K^T (warp: 16q x 32j), 4 k16 steps over d
        float sacc[4][4];
#pragma unroll
        for (int i = 0; i < 4; ++i)
#pragma unroll
            for (int j = 0; j < 4; ++j) sacc[i][j] = 0.f;
#pragma unroll
        for (int ks = 0; ks < 4; ++ks) {
            const int kd = ks * 8;
#pragma unroll
            for (int nt = 0; nt < 4; ++nt) {
                const int jn = wj * 32 + nt * 8;
                uint32_t bf[2];
                bf[0] = Kb[(jn + g) * AW + kd + t];
                bf[1] = Kb[(jn + g) * AW + kd + t + 4];
                mma_bf16(sacc[nt], qf[ks], bf);
            }
        }
        const float scale = 0.125f;
#pragma unroll
        for (int nt = 0; nt < 4; ++nt) {
            const int j = wj * 32 + nt * 8 + 2 * t;
            *(float2*)(Ss + (q0w + g) * SSP + j) =
                make_float2(sacc[nt][0] * scale, sacc[nt][1] * scale);
            *(float2*)(Ss + (q0w + g + 8) * SSP + j) =
                make_float2(sacc[nt][2] * scale, sacc[nt][3] * scale);
        }
        __syncthreads();

        // online softmax: 4 threads/row, 16 cols each; P -> bf16 pairs
        {
            const int q = tid >> 2;
            const int pt = tid & 3;
            const float* Sq = Ss + q * SSP + pt * 16;
            const float mo = ms[q];
            float mx = -1e30f;
#pragma unroll
            for (int i = 0; i < 16; ++i) mx = fmaxf(mx, Sq[i]);
            mx = fmaxf(mx, __shfl_xor_sync(0xffffffffu, mx, 1));
            mx = fmaxf(mx, __shfl_xor_sync(0xffffffffu, mx, 2));
            mx = fmaxf(mx, mo);
            float sum = 0.f;
            uint32_t* Pq = Pu + q * AW + pt * 8;
#pragma unroll
            for (int i = 0; i < 8; ++i) {
                const float e0 = __expf(Sq[2 * i]     - mx);
                const float e1 = __expf(Sq[2 * i + 1] - mx);
                sum += e0 + e1;
                Pq[i] = pack2(e0, e1);
            }
            sum += __shfl_xor_sync(0xffffffffu, sum, 1);
            sum += __shfl_xor_sync(0xffffffffu, sum, 2);
            if (pt == 0) {
                const float rr = __expf(mo - mx);
                ls[q] = ls[q] * rr + sum;
                ms[q] = mx;
                rs[q] = rr;
            }
        }
        __syncthreads();

        // rescale + O += P V (warp: 16q x 32d), 4 k16 steps over j
        const float rlo = rs[q0w + g];
        const float rhi = rs[q0w + g + 8];
#pragma unroll
        for (int nt = 0; nt < 4; ++nt) {
            accO[nt][0] *= rlo; accO[nt][1] *= rlo;
            accO[nt][2] *= rhi; accO[nt][3] *= rhi;
        }
#pragma unroll
        for (int ks = 0; ks < 4; ++ks) {
            const int kj = ks * 16;
            const int kw = ks * 8;
            uint32_t af[4];
            af[0] = Pu[(q0w + g) * AW + kw + t];
            af[1] = Pu[(q0w + g + 8) * AW + kw + t];
            af[2] = Pu[(q0w + g) * AW + kw + t + 4];
            af[3] = Pu[(q0w + g + 8) * AW + kw + t + 4];
#pragma unroll
            for (int half = 0; half < 2; ++half) {
                const int dn = wj * 32 + half * 16;
                uint32_t rr[4];
                ldsm4t(rr, vbase + ((kj + vrow) * AW) * 4 + (dn + vcol) * 2);
                mma_bf16(accO[half * 2 + 0], af, rr);
                mma_bf16(accO[half * 2 + 1], af, rr + 2);
            }
        }
    }

    // write bf16 ctx
    const float ilo = 1.0f / ls[q0w + g];
    const float ihi = 1.0f / ls[q0w + g + 8];
    __nv_bfloat16* Og = ctx + ((size_t)(b * SEQ + q0)) * D_MODEL + h * 64;
#pragma unroll
    for (int nt = 0; nt < 4; ++nt) {
        const int d = wj * 32 + nt * 8 + 2 * t;
        *(uint32_t*)(Og + (size_t)(q0w + g) * D_MODEL + d) =
            pack2(accO[nt][0] * ilo, accO[nt][1] * ilo);
        *(uint32_t*)(Og + (size_t)(q0w + g + 8) * D_MODEL + d) =
            pack2(accO[nt][2] * ihi, accO[nt][3] * ihi);
    }
}

// ------------------------- row LayerNorm (fp32 out + optional bf16) -------
__global__ __launch_bounds__(256) void ln_kernel(
    const float* __restrict__ y, const float* __restrict__ g,
    const float* __restrict__ be, float* __restrict__ o,
    uint32_t* __restrict__ ob)
{
    const int row = blockIdx.x;
    const float* x = y + (size_t)row * D_MODEL;
    const int t = threadIdx.x;
    float v0 = x[t], v1 = x[t + 256], v2 = x[t + 512];
    float s = v0 + v1 + v2;
    float q = v0 * v0 + v1 * v1 + v2 * v2;
#pragma unroll
    for (int off = 16; off; off >>= 1) {
        s += __shfl_xor_sync(0xffffffffu, s, off);
        q += __shfl_xor_sync(0xffffffffu, q, off);
    }
    __shared__ float ss[8], sq[8];
    __shared__ float s_mu, s_inv;
    int w = t >> 5, l = t & 31;
    if (l == 0) { ss[w] = s; sq[w] = q; }
    __syncthreads();
    if (t == 0) {
        float S = 0.f, Q = 0.f;
#pragma unroll
        for (int i = 0; i < 8; ++i) { S += ss[i]; Q += sq[i]; }
        float mu = S * (1.0f / D_MODEL);
        float var = Q * (1.0f / D_MODEL) - mu * mu;
        s_mu = mu;
        s_inv = rsqrtf(var + 1e-5f);
    }
    __syncthreads();
    const float mu = s_mu, inv = s_inv;
    float* op = o + (size_t)row * D_MODEL;
    op[t]       = (v0 - mu) * inv * g[t]       + be[t];
    op[t + 256] = (v1 - mu) * inv * g[t + 256] + be[t + 256];
    op[t + 512] = (v2 - mu) * inv * g[t + 512] + be[t + 512];
    if (ob) {
        uint32_t* obr = ob + (size_t)row * (D_MODEL / 2);
        {
            const int c = 2 * t;
            float a0 = (x[c] - mu) * inv * g[c] + be[c];
            float a1 = (x[c + 1] - mu) * inv * g[c + 1] + be[c + 1];
            obr[t] = pack2(a0, a1);
        }
        if (t < 128) {
            const int c = 512 + 2 * t;
            float a0 = (x[c] - mu) * inv * g[c] + be[c];
            float a1 = (x[c + 1] - mu) * inv * g[c + 1] + be[c + 1];
            obr[256 + t] = pack2(a0, a1);
        }
    }
}

// ------------------------- launch ----------------------------------------
extern "C" void kernel_launch(void* const* d_in, const int* in_sizes, int n_in,
                              void* d_out, int out_size)
{
    const float* src   = (const float*)d_in[0];
    const float* w_qkv = (const float*)d_in[1];
    const float* b_qkv = (const float*)d_in[2];
    const float* w_out = (const float*)d_in[3];
    const float* b_out = (const float*)d_in[4];
    const float* w1    = (const float*)d_in[5];
    const float* b1    = (const float*)d_in[6];
    const float* w2    = (const float*)d_in[7];
    const float* b2    = (const float*)d_in[8];
    const float* ln1w  = (const float*)d_in[9];
    const float* ln1b  = (const float*)d_in[10];
    const float* ln2w  = (const float*)d_in[11];
    const float* ln2b  = (const float*)d_in[12];
    float* out = (float*)d_out;

    float *y, *x;
    __nv_bfloat16 *srcb, *qkvb, *ctxb, *xb, *hb, *wqkvb, *woutb, *w1b, *w2b;
    cudaGetSymbolAddress((void**)&y,     g_y);
    cudaGetSymbolAddress((void**)&x,     g_x);
    cudaGetSymbolAddress((void**)&srcb,  g_srcb);
    cudaGetSymbolAddress((void**)&qkvb,  g_qkvb);
    cudaGetSymbolAddress((void**)&ctxb,  g_ctxb);
    cudaGetSymbolAddress((void**)&xb,    g_xb);
    cudaGetSymbolAddress((void**)&hb,    g_hb);
    cudaGetSymbolAddress((void**)&wqkvb, g_wqkvb);
    cudaGetSymbolAddress((void**)&woutb, g_woutb);
    cudaGetSymbolAddress((void**)&w1b,   g_w1b);
    cudaGetSymbolAddress((void**)&w2b,   g_w2b);

    cudaFuncSetAttribute(attn_tc,
                         cudaFuncAttributeMaxDynamicSharedMemorySize, ATTN_SMEM);

    // 0) one-time-per-launch bf16 conversions (weights + src)
    auto cvt = [](const float* s, __nv_bfloat16* d, int n) {
        int n4 = n / 4;
        f2b_kernel<<<(n4 + 255) / 256, 256>>>(s, (uint32_t*)d, n4);
    };
    cvt(src,   srcb,  MROWS * D_MODEL);
    cvt(w_qkv, wqkvb, D3 * D_MODEL);
    cvt(w_out, woutb, D_MODEL * D_MODEL);
    cvt(w1,    w1b,   DFF * D_MODEL);
    cvt(w2,    w2b,   D_MODEL * DFF);

    dim3 thr(256);
    // 1) QKV projection -> bf16 qkv
    gemm_tc<<<dim3(D3 / 128, MROWS / 128), thr>>>(
        srcb, wqkvb, b_qkv, nullptr, nullptr, qkvb, MROWS, D3, D_MODEL, 0);
    // 2) flash attention -> bf16 ctx
    attn_tc<<<dim3(SEQ / 64, BATCH * NHEAD), thr, ATTN_SMEM>>>(qkvb, ctxb);
    // 3) out projection + residual(src) -> fp32 y
    gemm_tc<<<dim3(D_MODEL / 128, MROWS / 128), thr>>>(
        ctxb, woutb, b_out, src, y, nullptr, MROWS, D_MODEL, D_MODEL, 0);
    // 4) LN1 -> fp32 x + bf16 xb
    ln_kernel<<<MROWS, 256>>>(y, ln1w, ln1b, x, (uint32_t*)xb);
    // 5) FFN1 + relu -> bf16 h
    gemm_tc<<<dim3(DFF / 128, MROWS / 128), thr>>>(
        xb, w1b, b1, nullptr, nullptr, hb, MROWS, DFF, D_MODEL, 1);
    // 6) FFN2 + residual(x) -> fp32 y
    gemm_tc<<<dim3(D_MODEL / 128, MROWS / 128), thr>>>(
        hb, w2b, b2, x, y, nullptr, MROWS, D_MODEL, DFF, 0);
    // 7) LN2 -> out
    ln_kernel<<<MROWS, 256>>>(y, ln2w, ln2b, out, nullptr);
}

// round 12
// speedup vs baseline: 2.2730x; 1.3390x over previous
#include <cuda_runtime.h>
#include <cuda_bf16.h>
#include <cstdint>

#define D_MODEL 768
#define D3      2304
#define DFF     3072
#define NHEAD   12
#define SEQ     4096
#define BATCH   2
#define MROWS   (BATCH*SEQ)   // 8192

// ------------------------- scratch (device globals; no runtime alloc) -----
__device__ float          g_y [MROWS * D_MODEL];
__device__ float          g_x [MROWS * D_MODEL];
__device__ __nv_bfloat16  g_srcb[MROWS * D_MODEL];
__device__ __nv_bfloat16  g_qkvb[MROWS * D3];
__device__ __nv_bfloat16  g_ctxb[MROWS * D_MODEL];
__device__ __nv_bfloat16  g_xb  [MROWS * D_MODEL];
__device__ __nv_bfloat16  g_hb  [MROWS * DFF];
__device__ __nv_bfloat16  g_wqkvb[D3 * D_MODEL];
__device__ __nv_bfloat16  g_woutb[D_MODEL * D_MODEL];
__device__ __nv_bfloat16  g_w1b  [DFF * D_MODEL];
__device__ __nv_bfloat16  g_w2b  [D_MODEL * DFF];

// ------------------------- helpers ---------------------------------------
__device__ __forceinline__ uint32_t pack2(float lo, float hi) {
    uint32_t r;
    asm("cvt.rn.bf16x2.f32 %0, %2, %1;" : "=r"(r) : "f"(lo), "f"(hi));
    return r;
}

__device__ __forceinline__ uint32_t mulbf2(uint32_t a, uint32_t b) {
    uint32_t r;
    asm("mul.rn.bf16x2 %0, %1, %2;" : "=r"(r) : "r"(a), "r"(b));
    return r;
}

__device__ __forceinline__ void mma_bf16(float* c, const uint32_t* a, const uint32_t* b) {
    asm volatile(
        "mma.sync.aligned.m16n8k16.row.col.f32.bf16.bf16.f32 "
        "{%0,%1,%2,%3},{%4,%5,%6,%7},{%8,%9},{%0,%1,%2,%3};"
        : "+f"(c[0]), "+f"(c[1]), "+f"(c[2]), "+f"(c[3])
        : "r"(a[0]), "r"(a[1]), "r"(a[2]), "r"(a[3]), "r"(b[0]), "r"(b[1]));
}

__device__ __forceinline__ uint32_t su32(const void* p) {
    return (uint32_t)__cvta_generic_to_shared(p);
}

__device__ __forceinline__ void cpa16(uint32_t dst, const void* src) {
    asm volatile("cp.async.cg.shared.global [%0], [%1], 16;" :: "r"(dst), "l"(src));
}
#define CP_COMMIT() asm volatile("cp.async.commit_group;" ::: "memory")
#define CP_WAIT0()  asm volatile("cp.async.wait_group 0;" ::: "memory")

__device__ __forceinline__ void ldsm4(uint32_t* r, uint32_t addr) {
    asm volatile(
        "ldmatrix.sync.aligned.m8n8.x4.shared.b16 {%0,%1,%2,%3}, [%4];"
        : "=r"(r[0]), "=r"(r[1]), "=r"(r[2]), "=r"(r[3]) : "r"(addr));
}

__device__ __forceinline__ void ldsm4t(uint32_t* r, uint32_t addr) {
    asm volatile(
        "ldmatrix.sync.aligned.m8n8.x4.trans.shared.b16 {%0,%1,%2,%3}, [%4];"
        : "=r"(r[0]), "=r"(r[1]), "=r"(r[2]), "=r"(r[3]) : "r"(addr));
}

// ------------------------- fp32 -> bf16 bulk convert ----------------------
__global__ __launch_bounds__(256) void f2b_kernel(
    const float* __restrict__ s, uint32_t* __restrict__ d, int n4)
{
    int i = blockIdx.x * blockDim.x + threadIdx.x;
    if (i < n4) {
        float4 v = ((const float4*)s)[i];
        d[2 * i]     = pack2(v.x, v.y);
        d[2 * i + 1] = pack2(v.z, v.w);
    }
}

// ------------------------- BF16 GEMM, cp.async pipelined (R11) ------------
#define GPW 20
#define GSTG (128 * GPW)

__global__ __launch_bounds__(256) void gemm_tc(
    const __nv_bfloat16* __restrict__ A, const __nv_bfloat16* __restrict__ W,
    const float* __restrict__ bias, const float* __restrict__ res,
    float* __restrict__ Cf, __nv_bfloat16* __restrict__ Cb,
    int M, int N, int K, int relu)
{
    __shared__ uint32_t As[2][GSTG];
    __shared__ uint32_t Bs[2][GSTG];

    const int tid  = threadIdx.x;
    const int warp = tid >> 5;
    const int lane = tid & 31;
    const int g = lane >> 2;
    const int t = lane & 3;
    const int wm = warp >> 2;
    const int wn = warp & 3;

    const int bm0 = blockIdx.y * 128;
    const int bn0 = blockIdx.x * 128;

    const int r  = tid >> 1;
    const int c2 = (tid & 1) * 2;
    const __nv_bfloat16* Ap = A + (size_t)(bm0 + r) * K + c2 * 8;
    const __nv_bfloat16* Wp = W + (size_t)(bn0 + r) * K + c2 * 8;
    const uint32_t dA = su32(As) + (r * GPW + c2 * 4) * 4;
    const uint32_t dB = su32(Bs) + (r * GPW + c2 * 4) * 4;

    float acc[4][4][4];
#pragma unroll
    for (int i = 0; i < 4; ++i)
#pragma unroll
        for (int j = 0; j < 4; ++j)
#pragma unroll
            for (int c = 0; c < 4; ++c) acc[i][j][c] = 0.f;

    const int NT = K / 32;

    cpa16(dA, Ap);      cpa16(dA + 16, Ap + 8);
    cpa16(dB, Wp);      cpa16(dB + 16, Wp + 8);
    CP_COMMIT();

    for (int it = 0; it < NT; ++it) {
        CP_WAIT0();
        __syncthreads();
        if (it + 1 < NT) {
            const int kc = (it + 1) * 32;
            const uint32_t so = (uint32_t)(((it + 1) & 1) * GSTG * 4);
            cpa16(dA + so, Ap + kc);      cpa16(dA + so + 16, Ap + kc + 8);
            cpa16(dB + so, Wp + kc);      cpa16(dB + so + 16, Wp + kc + 8);
            CP_COMMIT();
        }
        const uint32_t* as = As[it & 1];
        const uint32_t* bs = Bs[it & 1];
#pragma unroll
        for (int ks = 0; ks < 2; ++ks) {
            const int kd = ks * 8;
            uint32_t af[4][4], bf[4][2];
#pragma unroll
            for (int mt = 0; mt < 4; ++mt) {
                const int m = wm * 64 + mt * 16;
                af[mt][0] = as[(m + g) * GPW + kd + t];
                af[mt][1] = as[(m + g + 8) * GPW + kd + t];
                af[mt][2] = as[(m + g) * GPW + kd + t + 4];
                af[mt][3] = as[(m + g + 8) * GPW + kd + t + 4];
            }
#pragma unroll
            for (int nt = 0; nt < 4; ++nt) {
                const int n = wn * 32 + nt * 8;
                bf[nt][0] = bs[(n + g) * GPW + kd + t];
                bf[nt][1] = bs[(n + g) * GPW + kd + t + 4];
            }
#pragma unroll
            for (int mt = 0; mt < 4; ++mt)
#pragma unroll
                for (int nt = 0; nt < 4; ++nt)
                    mma_bf16(acc[mt][nt], af[mt], bf[nt]);
        }
    }

#pragma unroll
    for (int nt = 0; nt < 4; ++nt) {
        const int n = bn0 + wn * 32 + nt * 8 + 2 * t;
        const float2 bv = *(const float2*)(bias + n);
#pragma unroll
        for (int mt = 0; mt < 4; ++mt) {
            const int r0 = bm0 + wm * 64 + mt * 16 + g;
            const int r1 = r0 + 8;
            float2 v0 = make_float2(acc[mt][nt][0] + bv.x, acc[mt][nt][1] + bv.y);
            float2 v1 = make_float2(acc[mt][nt][2] + bv.x, acc[mt][nt][3] + bv.y);
            if (res) {
                float2 p0 = *(const float2*)(res + (size_t)r0 * N + n);
                float2 p1 = *(const float2*)(res + (size_t)r1 * N + n);
                v0.x += p0.x; v0.y += p0.y; v1.x += p1.x; v1.y += p1.y;
            }
            if (relu) {
                v0.x = fmaxf(v0.x, 0.f); v0.y = fmaxf(v0.y, 0.f);
                v1.x = fmaxf(v1.x, 0.f); v1.y = fmaxf(v1.y, 0.f);
            }
            if (Cf) {
                *(float2*)(Cf + (size_t)r0 * N + n) = v0;
                *(float2*)(Cf + (size_t)r1 * N + n) = v1;
            }
            if (Cb) {
                *(uint32_t*)(Cb + (size_t)r0 * N + n) = pack2(v0.x, v0.y);
                *(uint32_t*)(Cb + (size_t)r1 * N + n) = pack2(v1.x, v1.y);
            }
        }
    }
}

// ------------------------- BF16 flash attention (register FA-2) -----------
// Bq=128, Bk=64, dh=64. 8 warps, each owns 16q x 64j stripe.
// Softmax + stats fully in registers; P repacked from S fragments.
// smem = K/V double buffers only.
#define AW   36
#define KSTG (64 * AW)
#define ATTN_SMEM (4 * KSTG * 4)   // 36864 bytes

__global__ __launch_bounds__(256) void attn_tc(
    const __nv_bfloat16* __restrict__ qkv, __nv_bfloat16* __restrict__ ctx)
{
    extern __shared__ uint32_t smu[];
    const int tid  = threadIdx.x;
    const int lane = tid & 31;
    const int warp = tid >> 5;            // 0..7
    const int g = lane >> 2;
    const int t = lane & 3;
    const int q0w = warp * 16;

    const int bh = blockIdx.y;
    const int b = bh / NHEAD, h = bh % NHEAD;
    const int q0 = blockIdx.x * 128;
    const __nv_bfloat16* Qg = qkv + ((size_t)(b * SEQ + q0)) * D3 + h * 64;
    const __nv_bfloat16* Kg = qkv + ((size_t)(b * SEQ)) * D3 + D_MODEL + h * 64;
    const __nv_bfloat16* Vg = Kg + D_MODEL;

    // K/V cp.async mapping: 64 rows x 8 chunks(16B), 4 thr/row, 2 chunks each
    const int ar = tid >> 2;
    const int ac = (tid & 3) * 2;
    const uint32_t kdst = su32(smu) + (ar * AW + ac * 4) * 4;
    const uint32_t vdst = su32(smu) + (2 * KSTG + ar * AW + ac * 4) * 4;
    const __nv_bfloat16* Ksrc = Kg + (size_t)ar * D3 + ac * 8;
    const __nv_bfloat16* Vsrc = Vg + (size_t)ar * D3 + ac * 8;

    // stage 0 in flight
    cpa16(kdst, Ksrc);          cpa16(kdst + 16, Ksrc + 8);
    cpa16(vdst, Vsrc);          cpa16(vdst + 16, Vsrc + 8);
    CP_COMMIT();

    // Q fragments direct from global, pre-scaled by 1/sqrt(64)=0.125 (exact)
    uint32_t qf[4][4];
    {
        const uint32_t sc = 0x3E003E00u;   // bf16x2 {0.125, 0.125}
        const __nv_bfloat16* q_lo = Qg + (size_t)(q0w + g) * D3;
        const __nv_bfloat16* q_hi = Qg + (size_t)(q0w + g + 8) * D3;
#pragma unroll
        for (int ks = 0; ks < 4; ++ks) {
            qf[ks][0] = mulbf2(*(const uint32_t*)(q_lo + 16 * ks + 2 * t), sc);
            qf[ks][1] = mulbf2(*(const uint32_t*)(q_hi + 16 * ks + 2 * t), sc);
            qf[ks][2] = mulbf2(*(const uint32_t*)(q_lo + 16 * ks + 8 + 2 * t), sc);
            qf[ks][3] = mulbf2(*(const uint32_t*)(q_hi + 16 * ks + 8 + 2 * t), sc);
        }
    }

    // ldsm lane-address components
    const int brow = (lane & 7) + ((lane & 16) ? 8 : 0);   // K (non-trans)
    const int bword = (lane & 8) ? 4 : 0;
    const int vrow = (lane & 7) + ((lane & 8) ? 8 : 0);    // V (trans)
    const int vcol = (lane & 16) ? 8 : 0;

    float accO[8][4];
#pragma unroll
    for (int i = 0; i < 8; ++i)
#pragma unroll
        for (int j = 0; j < 4; ++j) accO[i][j] = 0.f;
    float m_lo = -1e30f, m_hi = -1e30f, l_lo = 0.f, l_hi = 0.f;

    const int NJT = SEQ / 64;
    for (int jt = 0; jt < NJT; ++jt) {
        CP_WAIT0();
        __syncthreads();
        if (jt + 1 < NJT) {
            const size_t jo = (size_t)(jt + 1) * 64 * D3;
            const uint32_t so = (uint32_t)(((jt + 1) & 1) * KSTG * 4);
            cpa16(kdst + so, Ksrc + jo);      cpa16(kdst + so + 16, Ksrc + jo + 8);
            cpa16(vdst + so, Vsrc + jo);      cpa16(vdst + so + 16, Vsrc + jo + 8);
            CP_COMMIT();
        }
        const uint32_t kb = su32(smu) + ((jt & 1) * KSTG) * 4;
        const uint32_t vb = su32(smu) + ((2 + (jt & 1)) * KSTG) * 4;

        // S = (Q*scale) K^T : warp 16q x 64j
        float sacc[8][4];
#pragma unroll
        for (int i = 0; i < 8; ++i)
#pragma unroll
            for (int j = 0; j < 4; ++j) sacc[i][j] = 0.f;
#pragma unroll
        for (int ks = 0; ks < 4; ++ks) {
            const int kd = ks * 8;
            uint32_t bfr[4][4];
#pragma unroll
            for (int p = 0; p < 4; ++p)
                ldsm4(bfr[p], kb + ((p * 16 + brow) * AW + kd + bword) * 4);
#pragma unroll
            for (int nt = 0; nt < 8; ++nt)
                mma_bf16(sacc[nt], qf[ks], &bfr[nt >> 1][(nt & 1) * 2]);
        }

        // register softmax (rows g, g+8; reduce across t-quad)
        float tl = -1e30f, th = -1e30f;
#pragma unroll
        for (int nt = 0; nt < 8; ++nt) {
            tl = fmaxf(tl, fmaxf(sacc[nt][0], sacc[nt][1]));
            th = fmaxf(th, fmaxf(sacc[nt][2], sacc[nt][3]));
        }
        tl = fmaxf(tl, __shfl_xor_sync(0xffffffffu, tl, 1));
        tl = fmaxf(tl, __shfl_xor_sync(0xffffffffu, tl, 2));
        th = fmaxf(th, __shfl_xor_sync(0xffffffffu, th, 1));
        th = fmaxf(th, __shfl_xor_sync(0xffffffffu, th, 2));
        const float mx_lo = fmaxf(m_lo, tl);
        const float mx_hi = fmaxf(m_hi, th);
        const float r_lo = __expf(m_lo - mx_lo);
        const float r_hi = __expf(m_hi - mx_hi);
        float s_lo = 0.f, s_hi = 0.f;
#pragma unroll
        for (int nt = 0; nt < 8; ++nt) {
            sacc[nt][0] = __expf(sacc[nt][0] - mx_lo);
            sacc[nt][1] = __expf(sacc[nt][1] - mx_lo);
            sacc[nt][2] = __expf(sacc[nt][2] - mx_hi);
            sacc[nt][3] = __expf(sacc[nt][3] - mx_hi);
            s_lo += sacc[nt][0] + sacc[nt][1];
            s_hi += sacc[nt][2] + sacc[nt][3];
        }
        s_lo += __shfl_xor_sync(0xffffffffu, s_lo, 1);
        s_lo += __shfl_xor_sync(0xffffffffu, s_lo, 2);
        s_hi += __shfl_xor_sync(0xffffffffu, s_hi, 1);
        s_hi += __shfl_xor_sync(0xffffffffu, s_hi, 2);
        l_lo = l_lo * r_lo + s_lo;   m_lo = mx_lo;
        l_hi = l_hi * r_hi + s_hi;   m_hi = mx_hi;

        // rescale accumulators
#pragma unroll
        for (int nt = 0; nt < 8; ++nt) {
            accO[nt][0] *= r_lo; accO[nt][1] *= r_lo;
            accO[nt][2] *= r_hi; accO[nt][3] *= r_hi;
        }

        // O += P V : P fragments repacked from sacc (C-frag -> A-frag identity)
#pragma unroll
        for (int c = 0; c < 4; ++c) {        // k-chunk of 16 j
            uint32_t af[4];
            af[0] = pack2(sacc[2 * c][0],     sacc[2 * c][1]);
            af[1] = pack2(sacc[2 * c][2],     sacc[2 * c][3]);
            af[2] = pack2(sacc[2 * c + 1][0], sacc[2 * c + 1][1]);
            af[3] = pack2(sacc[2 * c + 1][2], sacc[2 * c + 1][3]);
#pragma unroll
            for (int half = 0; half < 4; ++half) {   // 16 d per ldsm
                uint32_t rr[4];
                ldsm4t(rr, vb + ((16 * c + vrow) * AW) * 4 + (half * 16 + vcol) * 2);
                mma_bf16(accO[half * 2 + 0], af, rr);
                mma_bf16(accO[half * 2 + 1], af, rr + 2);
            }
        }
    }

    // write bf16 ctx
    const float ilo = 1.0f / l_lo;
    const float ihi = 1.0f / l_hi;
    __nv_bfloat16* Og = ctx + ((size_t)(b * SEQ + q0)) * D_MODEL + h * 64;
#pragma unroll
    for (int nt = 0; nt < 8; ++nt) {
        const int d = nt * 8 + 2 * t;
        *(uint32_t*)(Og + (size_t)(q0w + g) * D_MODEL + d) =
            pack2(accO[nt][0] * ilo, accO[nt][1] * ilo);
        *(uint32_t*)(Og + (size_t)(q0w + g + 8) * D_MODEL + d) =
            pack2(accO[nt][2] * ihi, accO[nt][3] * ihi);
    }
}

// ------------------------- row LayerNorm (fp32 out + optional bf16) -------
__global__ __launch_bounds__(256) void ln_kernel(
    const float* __restrict__ y, const float* __restrict__ g,
    const float* __restrict__ be, float* __restrict__ o,
    uint32_t* __restrict__ ob)
{
    const int row = blockIdx.x;
    const float* x = y + (size_t)row * D_MODEL;
    const int t = threadIdx.x;
    float v0 = x[t], v1 = x[t + 256], v2 = x[t + 512];
    float s = v0 + v1 + v2;
    float q = v0 * v0 + v1 * v1 + v2 * v2;
#pragma unroll
    for (int off = 16; off; off >>= 1) {
        s += __shfl_xor_sync(0xffffffffu, s, off);
        q += __shfl_xor_sync(0xffffffffu, q, off);
    }
    __shared__ float ss[8], sq[8];
    __shared__ float s_mu, s_inv;
    int w = t >> 5, l = t & 31;
    if (l == 0) { ss[w] = s; sq[w] = q; }
    __syncthreads();
    if (t == 0) {
        float S = 0.f, Q = 0.f;
#pragma unroll
        for (int i = 0; i < 8; ++i) { S += ss[i]; Q += sq[i]; }
        float mu = S * (1.0f / D_MODEL);
        float var = Q * (1.0f / D_MODEL) - mu * mu;
        s_mu = mu;
        s_inv = rsqrtf(var + 1e-5f);
    }
    __syncthreads();
    const float mu = s_mu, inv = s_inv;
    float* op = o + (size_t)row * D_MODEL;
    op[t]       = (v0 - mu) * inv * g[t]       + be[t];
    op[t + 256] = (v1 - mu) * inv * g[t + 256] + be[t + 256];
    op[t + 512] = (v2 - mu) * inv * g[t + 512] + be[t + 512];
    if (ob) {
        uint32_t* obr = ob + (size_t)row * (D_MODEL / 2);
        {
            const int c = 2 * t;
            float a0 = (x[c] - mu) * inv * g[c] + be[c];
            float a1 = (x[c + 1] - mu) * inv * g[c + 1] + be[c + 1];
            obr[t] = pack2(a0, a1);
        }
        if (t < 128) {
            const int c = 512 + 2 * t;
            float a0 = (x[c] - mu) * inv * g[c] + be[c];
            float a1 = (x[c + 1] - mu) * inv * g[c + 1] + be[c + 1];
            obr[256 + t] = pack2(a0, a1);
        }
    }
}

// ------------------------- launch ----------------------------------------
extern "C" void kernel_launch(void* const* d_in, const int* in_sizes, int n_in,
                              void* d_out, int out_size)
{
    const float* src   = (const float*)d_in[0];
    const float* w_qkv = (const float*)d_in[1];
    const float* b_qkv = (const float*)d_in[2];
    const float* w_out = (const float*)d_in[3];
    const float* b_out = (const float*)d_in[4];
    const float* w1    = (const float*)d_in[5];
    const float* b1    = (const float*)d_in[6];
    const float* w2    = (const float*)d_in[7];
    const float* b2    = (const float*)d_in[8];
    const float* ln1w  = (const float*)d_in[9];
    const float* ln1b  = (const float*)d_in[10];
    const float* ln2w  = (const float*)d_in[11];
    const float* ln2b  = (const float*)d_in[12];
    float* out = (float*)d_out;

    float *y, *x;
    __nv_bfloat16 *srcb, *qkvb, *ctxb, *xb, *hb, *wqkvb, *woutb, *w1b, *w2b;
    cudaGetSymbolAddress((void**)&y,     g_y);
    cudaGetSymbolAddress((void**)&x,     g_x);
    cudaGetSymbolAddress((void**)&srcb,  g_srcb);
    cudaGetSymbolAddress((void**)&qkvb,  g_qkvb);
    cudaGetSymbolAddress((void**)&ctxb,  g_ctxb);
    cudaGetSymbolAddress((void**)&xb,    g_xb);
    cudaGetSymbolAddress((void**)&hb,    g_hb);
    cudaGetSymbolAddress((void**)&wqkvb, g_wqkvb);
    cudaGetSymbolAddress((void**)&woutb, g_woutb);
    cudaGetSymbolAddress((void**)&w1b,   g_w1b);
    cudaGetSymbolAddress((void**)&w2b,   g_w2b);

    cudaFuncSetAttribute(attn_tc,
                         cudaFuncAttributeMaxDynamicSharedMemorySize, ATTN_SMEM);

    // 0) one-time-per-launch bf16 conversions (weights + src)
    auto cvt = [](const float* s, __nv_bfloat16* d, int n) {
        int n4 = n / 4;
        f2b_kernel<<<(n4 + 255) / 256, 256>>>(s, (uint32_t*)d, n4);
    };
    cvt(src,   srcb,  MROWS * D_MODEL);
    cvt(w_qkv, wqkvb, D3 * D_MODEL);
    cvt(w_out, woutb, D_MODEL * D_MODEL);
    cvt(w1,    w1b,   DFF * D_MODEL);
    cvt(w2,    w2b,   D_MODEL * DFF);

    dim3 thr(256);
    // 1) QKV projection -> bf16 qkv
    gemm_tc<<<dim3(D3 / 128, MROWS / 128), thr>>>(
        srcb, wqkvb, b_qkv, nullptr, nullptr, qkvb, MROWS, D3, D_MODEL, 0);
    // 2) flash attention (Bq=128, register softmax) -> bf16 ctx
    attn_tc<<<dim3(SEQ / 128, BATCH * NHEAD), thr, ATTN_SMEM>>>(qkvb, ctxb);
    // 3) out projection + residual(src) -> fp32 y
    gemm_tc<<<dim3(D_MODEL / 128, MROWS / 128), thr>>>(
        ctxb, woutb, b_out, src, y, nullptr, MROWS, D_MODEL, D_MODEL, 0);
    // 4) LN1 -> fp32 x + bf16 xb
    ln_kernel<<<MROWS, 256>>>(y, ln1w, ln1b, x, (uint32_t*)xb);
    // 5) FFN1 + relu -> bf16 h
    gemm_tc<<<dim3(DFF / 128, MROWS / 128), thr>>>(
        xb, w1b, b1, nullptr, nullptr, hb, MROWS, DFF, D_MODEL, 1);
    // 6) FFN2 + residual(x) -> fp32 y
    gemm_tc<<<dim3(D_MODEL / 128, MROWS / 128), thr>>>(
        hb, w2b, b2, x, y, nullptr, MROWS, D_MODEL, DFF, 0);
    // 7) LN2 -> out
    ln_kernel<<<MROWS, 256>>>(y, ln2w, ln2b, out, nullptr);
}

// round 13
// speedup vs baseline: 2.6292x; 1.1567x over previous
#include <cuda_runtime.h>
#include <cuda_bf16.h>
#include <cstdint>

#define D_MODEL 768
#define D3      2304
#define DFF     3072
#define NHEAD   12
#define SEQ     4096
#define BATCH   2
#define MROWS   (BATCH*SEQ)   // 8192

// ------------------------- scratch (device globals; no runtime alloc) -----
__device__ float          g_y [MROWS * D_MODEL];
__device__ float          g_x [MROWS * D_MODEL];
__device__ __nv_bfloat16  g_srcb[MROWS * D_MODEL];
__device__ __nv_bfloat16  g_qkvb[MROWS * D3];
__device__ __nv_bfloat16  g_ctxb[MROWS * D_MODEL];
__device__ __nv_bfloat16  g_xb  [MROWS * D_MODEL];
__device__ __nv_bfloat16  g_hb  [MROWS * DFF];
__device__ __nv_bfloat16  g_wqkvb[D3 * D_MODEL];
__device__ __nv_bfloat16  g_woutb[D_MODEL * D_MODEL];
__device__ __nv_bfloat16  g_w1b  [DFF * D_MODEL];
__device__ __nv_bfloat16  g_w2b  [D_MODEL * DFF];

// ------------------------- helpers ---------------------------------------
__device__ __forceinline__ uint32_t pack2(float lo, float hi) {
    uint32_t r;
    asm("cvt.rn.bf16x2.f32 %0, %2, %1;" : "=r"(r) : "f"(lo), "f"(hi));
    return r;
}

__device__ __forceinline__ uint32_t mulbf2(uint32_t a, uint32_t b) {
    uint32_t r;
    asm("mul.rn.bf16x2 %0, %1, %2;" : "=r"(r) : "r"(a), "r"(b));
    return r;
}

__device__ __forceinline__ void mma_bf16(float* c, const uint32_t* a, const uint32_t* b) {
    asm volatile(
        "mma.sync.aligned.m16n8k16.row.col.f32.bf16.bf16.f32 "
        "{%0,%1,%2,%3},{%4,%5,%6,%7},{%8,%9},{%0,%1,%2,%3};"
        : "+f"(c[0]), "+f"(c[1]), "+f"(c[2]), "+f"(c[3])
        : "r"(a[0]), "r"(a[1]), "r"(a[2]), "r"(a[3]), "r"(b[0]), "r"(b[1]));
}

__device__ __forceinline__ uint32_t su32(const void* p) {
    return (uint32_t)__cvta_generic_to_shared(p);
}

__device__ __forceinline__ void cpa16(uint32_t dst, const void* src) {
    asm volatile("cp.async.cg.shared.global [%0], [%1], 16;" :: "r"(dst), "l"(src));
}
#define CP_COMMIT() asm volatile("cp.async.commit_group;" ::: "memory")
#define CP_WAIT0()  asm volatile("cp.async.wait_group 0;" ::: "memory")

__device__ __forceinline__ void ldsm4(uint32_t* r, uint32_t addr) {
    asm volatile(
        "ldmatrix.sync.aligned.m8n8.x4.shared.b16 {%0,%1,%2,%3}, [%4];"
        : "=r"(r[0]), "=r"(r[1]), "=r"(r[2]), "=r"(r[3]) : "r"(addr));
}

__device__ __forceinline__ void ldsm4t(uint32_t* r, uint32_t addr) {
    asm volatile(
        "ldmatrix.sync.aligned.m8n8.x4.trans.shared.b16 {%0,%1,%2,%3}, [%4];"
        : "=r"(r[0]), "=r"(r[1]), "=r"(r[2]), "=r"(r[3]) : "r"(addr));
}

// ------------------------- fused fp32 -> bf16 convert (all 5 tensors) -----
#define N4_SRC  (MROWS * D_MODEL / 4)
#define N4_WQKV (D3 * D_MODEL / 4)
#define N4_WOUT (D_MODEL * D_MODEL / 4)
#define N4_W1   (DFF * D_MODEL / 4)
#define N4_W2   (D_MODEL * DFF / 4)
#define N4_ALL  (N4_SRC + N4_WQKV + N4_WOUT + N4_W1 + N4_W2)

__global__ __launch_bounds__(256) void f2b_all(
    const float* __restrict__ s_src, const float* __restrict__ s_wqkv,
    const float* __restrict__ s_wout, const float* __restrict__ s_w1,
    const float* __restrict__ s_w2,
    uint32_t* __restrict__ d_src, uint32_t* __restrict__ d_wqkv,
    uint32_t* __restrict__ d_wout, uint32_t* __restrict__ d_w1,
    uint32_t* __restrict__ d_w2)
{
    int i = blockIdx.x * blockDim.x + threadIdx.x;
    if (i >= N4_ALL) return;
    const float* s; uint32_t* d; int j = i;
    if (j < N4_SRC)                    { s = s_src;  d = d_src;  }
    else if ((j -= N4_SRC) < N4_WQKV)  { s = s_wqkv; d = d_wqkv; }
    else if ((j -= N4_WQKV) < N4_WOUT) { s = s_wout; d = d_wout; }
    else if ((j -= N4_WOUT) < N4_W1)   { s = s_w1;   d = d_w1;   }
    else { j -= N4_W1;                   s = s_w2;   d = d_w2;   }
    float4 v = ((const float4*)s)[j];
    d[2 * j]     = pack2(v.x, v.y);
    d[2 * j + 1] = pack2(v.z, v.w);
}

// ------------------------- BF16 GEMM: BK=64, ldmatrix, cp.async -----------
// C(MxN) = A(MxK) * W(NxK)^T + bias [+res f32][relu]; outputs fp32 and/or bf16.
// 128x128 tile, BK=64 elems (32 words/row, pad to 36), 256 threads, 2-stage.
#define GPW 36                       // words per row (32 data + 4 pad)
#define GSTG (128 * GPW)             // words per matrix per stage
#define GEMM_SMEM (4 * GSTG * 4)     // 73728 bytes

__global__ __launch_bounds__(256, 2) void gemm_tc(
    const __nv_bfloat16* __restrict__ A, const __nv_bfloat16* __restrict__ W,
    const float* __restrict__ bias, const float* __restrict__ res,
    float* __restrict__ Cf, __nv_bfloat16* __restrict__ Cb,
    int M, int N, int K, int relu)
{
    extern __shared__ uint32_t gsm[];
    const uint32_t sbase = su32(gsm);

    const int tid  = threadIdx.x;
    const int warp = tid >> 5;
    const int lane = tid & 31;
    const int g = lane >> 2;
    const int t = lane & 3;
    const int wm = warp >> 2;
    const int wn = warp & 3;

    const int bm0 = blockIdx.y * 128;
    const int bn0 = blockIdx.x * 128;

    // cp.async: 128 rows x 8 chunks(16B); 2 thr/row, 4 chunks each
    const int r    = tid >> 1;
    const int half = tid & 1;
    const __nv_bfloat16* Ap = A + (size_t)(bm0 + r) * K + half * 32;
    const __nv_bfloat16* Wp = W + (size_t)(bn0 + r) * K + half * 32;
    const uint32_t dA = sbase + (r * GPW + half * 16) * 4;
    const uint32_t dB = sbase + (2 * GSTG + r * GPW + half * 16) * 4;

    // ldmatrix lane-address components (R7-verified pattern)
    const int arow  = lane & 15;
    const int aword = (lane >> 4) << 2;
    const int brow  = (lane & 7) + ((lane & 16) ? 8 : 0);
    const int bword = (lane & 8) ? 4 : 0;
    const uint32_t aoff = sbase + ((wm * 64 + arow) * GPW + aword) * 4;
    const uint32_t boff = sbase + (2 * GSTG + (wn * 32 + brow) * GPW + bword) * 4;

    float acc[4][4][4];
#pragma unroll
    for (int i = 0; i < 4; ++i)
#pragma unroll
        for (int j = 0; j < 4; ++j)
#pragma unroll
            for (int c = 0; c < 4; ++c) acc[i][j][c] = 0.f;

    const int NT = K / 64;

    // prologue: stage 0
#pragma unroll
    for (int c = 0; c < 4; ++c) {
        cpa16(dA + c * 16, Ap + c * 8);
        cpa16(dB + c * 16, Wp + c * 8);
    }
    CP_COMMIT();

    for (int it = 0; it < NT; ++it) {
        CP_WAIT0();
        __syncthreads();
        if (it + 1 < NT) {
            const int kc = (it + 1) * 64;
            const uint32_t so = (uint32_t)(((it + 1) & 1) * GSTG * 4);
#pragma unroll
            for (int c = 0; c < 4; ++c) {
                cpa16(dA + so + c * 16, Ap + kc + c * 8);
                cpa16(dB + so + c * 16, Wp + kc + c * 8);
            }
            CP_COMMIT();
        }
        const uint32_t abase = aoff + (uint32_t)((it & 1) * GSTG * 4);
        const uint32_t bbase = boff + (uint32_t)((it & 1) * GSTG * 4);
#pragma unroll
        for (int ks = 0; ks < 4; ++ks) {
            const int kd = ks * 8;
            uint32_t af[4][4], bfr[2][4];
#pragma unroll
            for (int mt = 0; mt < 4; ++mt)
                ldsm4(af[mt], abase + (mt * 16 * GPW + kd) * 4);
#pragma unroll
            for (int p = 0; p < 2; ++p)
                ldsm4(bfr[p], bbase + (p * 16 * GPW + kd) * 4);
#pragma unroll
            for (int mt = 0; mt < 4; ++mt)
#pragma unroll
                for (int nt = 0; nt < 4; ++nt)
                    mma_bf16(acc[mt][nt], af[mt], &bfr[nt >> 1][(nt & 1) * 2]);
        }
    }

    // epilogue: bias + optional residual + relu; fp32 and/or bf16 stores
#pragma unroll
    for (int nt = 0; nt < 4; ++nt) {
        const int n = bn0 + wn * 32 + nt * 8 + 2 * t;
        const float2 bv = *(const float2*)(bias + n);
#pragma unroll
        for (int mt = 0; mt < 4; ++mt) {
            const int r0 = bm0 + wm * 64 + mt * 16 + g;
            const int r1 = r0 + 8;
            float2 v0 = make_float2(acc[mt][nt][0] + bv.x, acc[mt][nt][1] + bv.y);
            float2 v1 = make_float2(acc[mt][nt][2] + bv.x, acc[mt][nt][3] + bv.y);
            if (res) {
                float2 p0 = *(const float2*)(res + (size_t)r0 * N + n);
                float2 p1 = *(const float2*)(res + (size_t)r1 * N + n);
                v0.x += p0.x; v0.y += p0.y; v1.x += p1.x; v1.y += p1.y;
            }
            if (relu) {
                v0.x = fmaxf(v0.x, 0.f); v0.y = fmaxf(v0.y, 0.f);
                v1.x = fmaxf(v1.x, 0.f); v1.y = fmaxf(v1.y, 0.f);
            }
            if (Cf) {
                *(float2*)(Cf + (size_t)r0 * N + n) = v0;
                *(float2*)(Cf + (size_t)r1 * N + n) = v1;
            }
            if (Cb) {
                *(uint32_t*)(Cb + (size_t)r0 * N + n) = pack2(v0.x, v0.y);
                *(uint32_t*)(Cb + (size_t)r1 * N + n) = pack2(v1.x, v1.y);
            }
        }
    }
}

// ------------------------- BF16 flash attention (register FA-2, R12) ------
#define AW   36
#define KSTG (64 * AW)
#define ATTN_SMEM (4 * KSTG * 4)   // 36864 bytes

__global__ __launch_bounds__(256) void attn_tc(
    const __nv_bfloat16* __restrict__ qkv, __nv_bfloat16* __restrict__ ctx)
{
    extern __shared__ uint32_t smu[];
    const int tid  = threadIdx.x;
    const int lane = tid & 31;
    const int warp = tid >> 5;            // 0..7
    const int g = lane >> 2;
    const int t = lane & 3;
    const int q0w = warp * 16;

    const int bh = blockIdx.y;
    const int b = bh / NHEAD, h = bh % NHEAD;
    const int q0 = blockIdx.x * 128;
    const __nv_bfloat16* Qg = qkv + ((size_t)(b * SEQ + q0)) * D3 + h * 64;
    const __nv_bfloat16* Kg = qkv + ((size_t)(b * SEQ)) * D3 + D_MODEL + h * 64;
    const __nv_bfloat16* Vg = Kg + D_MODEL;

    const int ar = tid >> 2;
    const int ac = (tid & 3) * 2;
    const uint32_t kdst = su32(smu) + (ar * AW + ac * 4) * 4;
    const uint32_t vdst = su32(smu) + (2 * KSTG + ar * AW + ac * 4) * 4;
    const __nv_bfloat16* Ksrc = Kg + (size_t)ar * D3 + ac * 8;
    const __nv_bfloat16* Vsrc = Vg + (size_t)ar * D3 + ac * 8;

    cpa16(kdst, Ksrc);          cpa16(kdst + 16, Ksrc + 8);
    cpa16(vdst, Vsrc);          cpa16(vdst + 16, Vsrc + 8);
    CP_COMMIT();

    uint32_t qf[4][4];
    {
        const uint32_t sc = 0x3E003E00u;   // bf16x2 {0.125, 0.125}
        const __nv_bfloat16* q_lo = Qg + (size_t)(q0w + g) * D3;
        const __nv_bfloat16* q_hi = Qg + (size_t)(q0w + g + 8) * D3;
#pragma unroll
        for (int ks = 0; ks < 4; ++ks) {
            qf[ks][0] = mulbf2(*(const uint32_t*)(q_lo + 16 * ks + 2 * t), sc);
            qf[ks][1] = mulbf2(*(const uint32_t*)(q_hi + 16 * ks + 2 * t), sc);
            qf[ks][2] = mulbf2(*(const uint32_t*)(q_lo + 16 * ks + 8 + 2 * t), sc);
            qf[ks][3] = mulbf2(*(const uint32_t*)(q_hi + 16 * ks + 8 + 2 * t), sc);
        }
    }

    const int brow = (lane & 7) + ((lane & 16) ? 8 : 0);
    const int bword = (lane & 8) ? 4 : 0;
    const int vrow = (lane & 7) + ((lane & 8) ? 8 : 0);
    const int vcol = (lane & 16) ? 8 : 0;

    float accO[8][4];
#pragma unroll
    for (int i = 0; i < 8; ++i)
#pragma unroll
        for (int j = 0; j < 4; ++j) accO[i][j] = 0.f;
    float m_lo = -1e30f, m_hi = -1e30f, l_lo = 0.f, l_hi = 0.f;

    const int NJT = SEQ / 64;
    for (int jt = 0; jt < NJT; ++jt) {
        CP_WAIT0();
        __syncthreads();
        if (jt + 1 < NJT) {
            const size_t jo = (size_t)(jt + 1) * 64 * D3;
            const uint32_t so = (uint32_t)(((jt + 1) & 1) * KSTG * 4);
            cpa16(kdst + so, Ksrc + jo);      cpa16(kdst + so + 16, Ksrc + jo + 8);
            cpa16(vdst + so, Vsrc + jo);      cpa16(vdst + so + 16, Vsrc + jo + 8);
            CP_COMMIT();
        }
        const uint32_t kb = su32(smu) + ((jt & 1) * KSTG) * 4;
        const uint32_t vb = su32(smu) + ((2 + (jt & 1)) * KSTG) * 4;

        float sacc[8][4];
#pragma unroll
        for (int i = 0; i < 8; ++i)
#pragma unroll
            for (int j = 0; j < 4; ++j) sacc[i][j] = 0.f;
#pragma unroll
        for (int ks = 0; ks < 4; ++ks) {
            const int kd = ks * 8;
            uint32_t bfr[4][4];
#pragma unroll
            for (int p = 0; p < 4; ++p)
                ldsm4(bfr[p], kb + ((p * 16 + brow) * AW + kd + bword) * 4);
#pragma unroll
            for (int nt = 0; nt < 8; ++nt)
                mma_bf16(sacc[nt], qf[ks], &bfr[nt >> 1][(nt & 1) * 2]);
        }

        float tl = -1e30f, th = -1e30f;
#pragma unroll
        for (int nt = 0; nt < 8; ++nt) {
            tl = fmaxf(tl, fmaxf(sacc[nt][0], sacc[nt][1]));
            th = fmaxf(th, fmaxf(sacc[nt][2], sacc[nt][3]));
        }
        tl = fmaxf(tl, __shfl_xor_sync(0xffffffffu, tl, 1));
        tl = fmaxf(tl, __shfl_xor_sync(0xffffffffu, tl, 2));
        th = fmaxf(th, __shfl_xor_sync(0xffffffffu, th, 1));
        th = fmaxf(th, __shfl_xor_sync(0xffffffffu, th, 2));
        const float mx_lo = fmaxf(m_lo, tl);
        const float mx_hi = fmaxf(m_hi, th);
        const float r_lo = __expf(m_lo - mx_lo);
        const float r_hi = __expf(m_hi - mx_hi);
        float s_lo = 0.f, s_hi = 0.f;
#pragma unroll
        for (int nt = 0; nt < 8; ++nt) {
            sacc[nt][0] = __expf(sacc[nt][0] - mx_lo);
            sacc[nt][1] = __expf(sacc[nt][1] - mx_lo);
            sacc[nt][2] = __expf(sacc[nt][2] - mx_hi);
            sacc[nt][3] = __expf(sacc[nt][3] - mx_hi);
            s_lo += sacc[nt][0] + sacc[nt][1];
            s_hi += sacc[nt][2] + sacc[nt][3];
        }
        s_lo += __shfl_xor_sync(0xffffffffu, s_lo, 1);
        s_lo += __shfl_xor_sync(0xffffffffu, s_lo, 2);
        s_hi += __shfl_xor_sync(0xffffffffu, s_hi, 1);
        s_hi += __shfl_xor_sync(0xffffffffu, s_hi, 2);
        l_lo = l_lo * r_lo + s_lo;   m_lo = mx_lo;
        l_hi = l_hi * r_hi + s_hi;   m_hi = mx_hi;

#pragma unroll
        for (int nt = 0; nt < 8; ++nt) {
            accO[nt][0] *= r_lo; accO[nt][1] *= r_lo;
            accO[nt][2] *= r_hi; accO[nt][3] *= r_hi;
        }

#pragma unroll
        for (int c = 0; c < 4; ++c) {
            uint32_t af[4];
            af[0] = pack2(sacc[2 * c][0],     sacc[2 * c][1]);
            af[1] = pack2(sacc[2 * c][2],     sacc[2 * c][3]);
            af[2] = pack2(sacc[2 * c + 1][0], sacc[2 * c + 1][1]);
            af[3] = pack2(sacc[2 * c + 1][2], sacc[2 * c + 1][3]);
#pragma unroll
            for (int halfd = 0; halfd < 4; ++halfd) {
                uint32_t rr[4];
                ldsm4t(rr, vb + ((16 * c + vrow) * AW) * 4 + (halfd * 16 + vcol) * 2);
                mma_bf16(accO[halfd * 2 + 0], af, rr);
                mma_bf16(accO[halfd * 2 + 1], af, rr + 2);
            }
        }
    }

    const float ilo = 1.0f / l_lo;
    const float ihi = 1.0f / l_hi;
    __nv_bfloat16* Og = ctx + ((size_t)(b * SEQ + q0)) * D_MODEL + h * 64;
#pragma unroll
    for (int nt = 0; nt < 8; ++nt) {
        const int d = nt * 8 + 2 * t;
        *(uint32_t*)(Og + (size_t)(q0w + g) * D_MODEL + d) =
            pack2(accO[nt][0] * ilo, accO[nt][1] * ilo);
        *(uint32_t*)(Og + (size_t)(q0w + g + 8) * D_MODEL + d) =
            pack2(accO[nt][2] * ihi, accO[nt][3] * ihi);
    }
}

// ------------------------- row LayerNorm (fp32 out + optional bf16) -------
__global__ __launch_bounds__(256) void ln_kernel(
    const float* __restrict__ y, const float* __restrict__ g,
    const float* __restrict__ be, float* __restrict__ o,
    uint32_t* __restrict__ ob)
{
    const int row = blockIdx.x;
    const float* x = y + (size_t)row * D_MODEL;
    const int t = threadIdx.x;
    float v0 = x[t], v1 = x[t + 256], v2 = x[t + 512];
    float s = v0 + v1 + v2;
    float q = v0 * v0 + v1 * v1 + v2 * v2;
#pragma unroll
    for (int off = 16; off; off >>= 1) {
        s += __shfl_xor_sync(0xffffffffu, s, off);
        q += __shfl_xor_sync(0xffffffffu, q, off);
    }
    __shared__ float ss[8], sq[8];
    __shared__ float s_mu, s_inv;
    int w = t >> 5, l = t & 31;
    if (l == 0) { ss[w] = s; sq[w] = q; }
    __syncthreads();
    if (t == 0) {
        float S = 0.f, Q = 0.f;
#pragma unroll
        for (int i = 0; i < 8; ++i) { S += ss[i]; Q += sq[i]; }
        float mu = S * (1.0f / D_MODEL);
        float var = Q * (1.0f / D_MODEL) - mu * mu;
        s_mu = mu;
        s_inv = rsqrtf(var + 1e-5f);
    }
    __syncthreads();
    const float mu = s_mu, inv = s_inv;
    float* op = o + (size_t)row * D_MODEL;
    op[t]       = (v0 - mu) * inv * g[t]       + be[t];
    op[t + 256] = (v1 - mu) * inv * g[t + 256] + be[t + 256];
    op[t + 512] = (v2 - mu) * inv * g[t + 512] + be[t + 512];
    if (ob) {
        uint32_t* obr = ob + (size_t)row * (D_MODEL / 2);
        {
            const int c = 2 * t;
            float a0 = (x[c] - mu) * inv * g[c] + be[c];
            float a1 = (x[c + 1] - mu) * inv * g[c + 1] + be[c + 1];
            obr[t] = pack2(a0, a1);
        }
        if (t < 128) {
            const int c = 512 + 2 * t;
            float a0 = (x[c] - mu) * inv * g[c] + be[c];
            float a1 = (x[c + 1] - mu) * inv * g[c + 1] + be[c + 1];
            obr[256 + t] = pack2(a0, a1);
        }
    }
}

// ------------------------- launch ----------------------------------------
extern "C" void kernel_launch(void* const* d_in, const int* in_sizes, int n_in,
                              void* d_out, int out_size)
{
    const float* src   = (const float*)d_in[0];
    const float* w_qkv = (const float*)d_in[1];
    const float* b_qkv = (const float*)d_in[2];
    const float* w_out = (const float*)d_in[3];
    const float* b_out = (const float*)d_in[4];
    const float* w1    = (const float*)d_in[5];
    const float* b1    = (const float*)d_in[6];
    const float* w2    = (const float*)d_in[7];
    const float* b2    = (const float*)d_in[8];
    const float* ln1w  = (const float*)d_in[9];
    const float* ln1b  = (const float*)d_in[10];
    const float* ln2w  = (const float*)d_in[11];
    const float* ln2b  = (const float*)d_in[12];
    float* out = (float*)d_out;

    float *y, *x;
    __nv_bfloat16 *srcb, *qkvb, *ctxb, *xb, *hb, *wqkvb, *woutb, *w1b, *w2b;
    cudaGetSymbolAddress((void**)&y,     g_y);
    cudaGetSymbolAddress((void**)&x,     g_x);
    cudaGetSymbolAddress((void**)&srcb,  g_srcb);
    cudaGetSymbolAddress((void**)&qkvb,  g_qkvb);
    cudaGetSymbolAddress((void**)&ctxb,  g_ctxb);
    cudaGetSymbolAddress((void**)&xb,    g_xb);
    cudaGetSymbolAddress((void**)&hb,    g_hb);
    cudaGetSymbolAddress((void**)&wqkvb, g_wqkvb);
    cudaGetSymbolAddress((void**)&woutb, g_woutb);
    cudaGetSymbolAddress((void**)&w1b,   g_w1b);
    cudaGetSymbolAddress((void**)&w2b,   g_w2b);

    cudaFuncSetAttribute(gemm_tc,
                         cudaFuncAttributeMaxDynamicSharedMemorySize, GEMM_SMEM);
    cudaFuncSetAttribute(attn_tc,
                         cudaFuncAttributeMaxDynamicSharedMemorySize, ATTN_SMEM);

    dim3 thr(256);
    // 0) fused one-time bf16 conversions
    f2b_all<<<(N4_ALL + 255) / 256, thr>>>(
        src, w_qkv, w_out, w1, w2,
        (uint32_t*)srcb, (uint32_t*)wqkvb, (uint32_t*)woutb,
        (uint32_t*)w1b, (uint32_t*)w2b);

    // 1) QKV projection -> bf16 qkv
    gemm_tc<<<dim3(D3 / 128, MROWS / 128), thr, GEMM_SMEM>>>(
        srcb, wqkvb, b_qkv, nullptr, nullptr, qkvb, MROWS, D3, D_MODEL, 0);
    // 2) flash attention (Bq=128, register softmax) -> bf16 ctx
    attn_tc<<<dim3(SEQ / 128, BATCH * NHEAD), thr, ATTN_SMEM>>>(qkvb, ctxb);
    // 3) out projection + residual(src) -> fp32 y
    gemm_tc<<<dim3(D_MODEL / 128, MROWS / 128), thr, GEMM_SMEM>>>(
        ctxb, woutb, b_out, src, y, nullptr, MROWS, D_MODEL, D_MODEL, 0);
    // 4) LN1 -> fp32 x + bf16 xb
    ln_kernel<<<MROWS, 256>>>(y, ln1w, ln1b, x, (uint32_t*)xb);
    // 5) FFN1 + relu -> bf16 h
    gemm_tc<<<dim3(DFF / 128, MROWS / 128), thr, GEMM_SMEM>>>(
        xb, w1b, b1, nullptr, nullptr, hb, MROWS, DFF, D_MODEL, 1);
    // 6) FFN2 + residual(x) -> fp32 y
    gemm_tc<<<dim3(D_MODEL / 128, MROWS / 128), thr, GEMM_SMEM>>>(
        hb, w2b, b2, x, y, nullptr, MROWS, D_MODEL, DFF, 0);
    // 7) LN2 -> out
    ln_kernel<<<MROWS, 256>>>(y, ln2w, ln2b, out, nullptr);
}